// round 8
// baseline (speedup 1.0000x reference)
#include <cuda_runtime.h>
#include <cuda_bf16.h>
#include <cstdint>
#include <math.h>

#define N_NODES 100000
#define N_EDGES 819200
#define D 512
#define L_LAYERS 3
#define LN_EPS 1e-5f
#define SCAN_BS 512
#define SCAN_NBLK ((N_NODES + SCAN_BS - 1) / SCAN_BS)   // 196

// ---------------- scratch (static device globals; no allocation) ------------
__device__ float g_h1 [(size_t)N_NODES * D];
__device__ float g_h2 [(size_t)N_NODES * D];
__device__ float g_x0 [(size_t)N_NODES * D];
__device__ float g_x1 [(size_t)N_NODES * D];
__device__ float g_inv[N_NODES];
__device__ int   g_deg[N_NODES];
__device__ int   g_rp [N_NODES];
__device__ int   g_cur[N_NODES];
__device__ int   g_bsum[256];
__device__ int   g_adj[N_EDGES];
__device__ __align__(16) __nv_bfloat16 g_aH[(size_t)N_NODES * D];
__device__ __align__(16) __nv_bfloat16 g_aL[(size_t)N_NODES * D];
__device__ __align__(16) __nv_bfloat16 g_xH[(size_t)N_NODES * D];
__device__ __align__(16) __nv_bfloat16 g_xL[(size_t)N_NODES * D];
__device__ __align__(16) __nv_bfloat16 g_wlH[L_LAYERS * D * D];
__device__ __align__(16) __nv_bfloat16 g_wlL[L_LAYERS * D * D];
__device__ __align__(16) __nv_bfloat16 g_wrH[L_LAYERS * D * D];
__device__ __align__(16) __nv_bfloat16 g_wrL[L_LAYERS * D * D];

// ---------------- helpers ---------------------------------------------------
__device__ __forceinline__ uint32_t smem_u32(const void* p) {
    uint32_t a;
    asm("{ .reg .u64 t; cvta.to.shared.u64 t, %1; cvt.u32.u64 %0, t; }"
        : "=r"(a) : "l"(p));
    return a;
}
__device__ __forceinline__ uint32_t pk(__nv_bfloat16 a, __nv_bfloat16 b) {
    uint16_t ua = *(uint16_t*)&a, ub = *(uint16_t*)&b;
    return (uint32_t)ua | ((uint32_t)ub << 16);
}
__device__ __forceinline__ void ldsm4(uint32_t* r, uint32_t addr) {
    asm volatile("ldmatrix.sync.aligned.m8n8.x4.shared.b16 {%0,%1,%2,%3}, [%4];"
                 : "=r"(r[0]), "=r"(r[1]), "=r"(r[2]), "=r"(r[3]) : "r"(addr));
}
__device__ __forceinline__ void mma16816(float* c, const uint32_t* a, const uint32_t* b) {
    asm volatile("mma.sync.aligned.m16n8k16.row.col.f32.bf16.bf16.f32 "
                 "{%0,%1,%2,%3}, {%4,%5,%6,%7}, {%8,%9}, {%0,%1,%2,%3};"
                 : "+f"(c[0]), "+f"(c[1]), "+f"(c[2]), "+f"(c[3])
                 : "r"(a[0]), "r"(a[1]), "r"(a[2]), "r"(a[3]), "r"(b[0]), "r"(b[1]));
}
__device__ __forceinline__ void cp16(uint32_t dst, const void* src, uint32_t bytes) {
    asm volatile("cp.async.cg.shared.global [%0], [%1], 16, %2;"
                 :: "r"(dst), "l"(src), "r"(bytes) : "memory");
}
#define CP_COMMIT() asm volatile("cp.async.commit_group;" ::: "memory")
#define CP_WAIT2()  asm volatile("cp.async.wait_group 2;" ::: "memory")

__device__ __forceinline__ void split2(float v, __nv_bfloat16& h, __nv_bfloat16& l) {
    h = __float2bfloat16_rn(v);
    l = __float2bfloat16_rn(v - __bfloat162float(h));
}

// ---------------- CSR build -------------------------------------------------
__global__ void zero_deg_kernel(int* __restrict__ deg) {
    int i = blockIdx.x * blockDim.x + threadIdx.x;
    if (i < N_NODES) deg[i] = 0;
}
__global__ void count_kernel(const int* __restrict__ ei, int* __restrict__ deg) {
    int e = blockIdx.x * blockDim.x + threadIdx.x;
    if (e < N_EDGES) atomicAdd(&deg[ei[N_EDGES + e]], 1);
}
__global__ void __launch_bounds__(SCAN_BS) scan1_kernel(
    const int* __restrict__ deg, int* __restrict__ rp, int* __restrict__ bsum)
{
    __shared__ int sh[SCAN_BS];
    int t = threadIdx.x;
    int i = blockIdx.x * SCAN_BS + t;
    int v = (i < N_NODES) ? deg[i] : 0;
    sh[t] = v; __syncthreads();
    for (int off = 1; off < SCAN_BS; off <<= 1) {
        int u = (t >= off) ? sh[t - off] : 0;
        __syncthreads();
        sh[t] += u;
        __syncthreads();
    }
    if (i < N_NODES) rp[i] = sh[t] - v;
    if (t == SCAN_BS - 1) bsum[blockIdx.x] = sh[t];
}
__global__ void __launch_bounds__(256) scan2_kernel(int* __restrict__ bsum) {
    __shared__ int sh[256];
    int t = threadIdx.x;
    int v = (t < SCAN_NBLK) ? bsum[t] : 0;
    sh[t] = v; __syncthreads();
    for (int off = 1; off < 256; off <<= 1) {
        int u = (t >= off) ? sh[t - off] : 0;
        __syncthreads();
        sh[t] += u;
        __syncthreads();
    }
    if (t < SCAN_NBLK) bsum[t] = sh[t] - v;
}
__global__ void scan3_kernel(const int* __restrict__ deg, int* __restrict__ rp,
                             int* __restrict__ cur, float* __restrict__ inv,
                             const int* __restrict__ bsum)
{
    int i = blockIdx.x * blockDim.x + threadIdx.x;
    if (i < N_NODES) {
        int r = rp[i] + bsum[i >> 9];
        rp[i] = r;
        cur[i] = r;
        inv[i] = 1.0f / (float)max(deg[i], 1);
    }
}
__global__ void fill_kernel(const int* __restrict__ ei, int* __restrict__ cur,
                            int* __restrict__ adj)
{
    int e = blockIdx.x * blockDim.x + threadIdx.x;
    if (e < N_EDGES) {
        int slot = atomicAdd(&cur[ei[N_EDGES + e]], 1);
        adj[slot] = ei[e];
    }
}

// ---------------- CSR gather aggregation + mean + bf16 split ----------------
__global__ void __launch_bounds__(256) agg_kernel(
    const float* __restrict__ x, const int* __restrict__ rp,
    const int* __restrict__ deg, const float* __restrict__ inv,
    const int* __restrict__ adj,
    __nv_bfloat16* __restrict__ hi, __nv_bfloat16* __restrict__ lo)
{
    int node = blockIdx.x * 8 + (threadIdx.x >> 5);
    if (node >= N_NODES) return;
    int lane = threadIdx.x & 31;

    float4 acc[4];
#pragma unroll
    for (int q = 0; q < 4; q++) acc[q] = make_float4(0.f, 0.f, 0.f, 0.f);

    int beg = __ldg(&rp[node]);
    int d   = __ldg(&deg[node]);
    int j = 0;
    for (; j + 2 <= d; j += 2) {
        int s0 = __ldg(&adj[beg + j]);
        int s1 = __ldg(&adj[beg + j + 1]);
        const float4* r0 = (const float4*)(x + (size_t)s0 * D);
        const float4* r1 = (const float4*)(x + (size_t)s1 * D);
        float4 v0[4], v1[4];
#pragma unroll
        for (int q = 0; q < 4; q++) v0[q] = __ldg(r0 + lane + q * 32);
#pragma unroll
        for (int q = 0; q < 4; q++) v1[q] = __ldg(r1 + lane + q * 32);
#pragma unroll
        for (int q = 0; q < 4; q++) {
            acc[q].x += v0[q].x + v1[q].x;
            acc[q].y += v0[q].y + v1[q].y;
            acc[q].z += v0[q].z + v1[q].z;
            acc[q].w += v0[q].w + v1[q].w;
        }
    }
    if (j < d) {
        int s0 = __ldg(&adj[beg + j]);
        const float4* r0 = (const float4*)(x + (size_t)s0 * D);
#pragma unroll
        for (int q = 0; q < 4; q++) {
            float4 v = __ldg(r0 + lane + q * 32);
            acc[q].x += v.x; acc[q].y += v.y; acc[q].z += v.z; acc[q].w += v.w;
        }
    }
    float s = __ldg(&inv[node]);
    uint2* ph = (uint2*)(hi + (size_t)node * D);
    uint2* pl = (uint2*)(lo + (size_t)node * D);
#pragma unroll
    for (int q = 0; q < 4; q++) {
        float4 v = acc[q];
        v.x *= s; v.y *= s; v.z *= s; v.w *= s;
        __nv_bfloat16 h0, h1, h2, h3, l0, l1, l2, l3;
        split2(v.x, h0, l0); split2(v.y, h1, l1);
        split2(v.z, h2, l2); split2(v.w, h3, l3);
        ph[lane + q * 32] = make_uint2(pk(h0, h1), pk(h2, h3));
        pl[lane + q * 32] = make_uint2(pk(l0, l1), pk(l2, l3));
    }
}

// ---------------- fp32 -> (bf16 hi, bf16 lo) split --------------------------
__global__ void __launch_bounds__(128) split_kernel(
    const float* __restrict__ in,
    __nv_bfloat16* __restrict__ hi, __nv_bfloat16* __restrict__ lo)
{
    size_t row = blockIdx.x;
    int t = threadIdx.x;
    float4 v = ((const float4*)(in + row * D))[t];
    __nv_bfloat16 h0, h1, h2, h3, l0, l1, l2, l3;
    split2(v.x, h0, l0); split2(v.y, h1, l1);
    split2(v.z, h2, l2); split2(v.w, h3, l3);
    ((uint2*)(hi + row * D))[t] = make_uint2(pk(h0, h1), pk(h2, h3));
    ((uint2*)(lo + row * D))[t] = make_uint2(pk(l0, l1), pk(l2, l3));
}

// ---------------- bf16-split tensor-core GEMM (single product, K=512) -------
// Out[m0:+128, n0:+128] = A @ W^T (+ bias if non-null)
// A,W pre-split (hi,lo); products Ah*Bh + Al*Bh + Ah*Bl.
#define NSTAGE 4
#define N_CHUNK 16
#define A_TILE 16384
#define STAGE_B 32768
#define GEMM_SMEM (NSTAGE * STAGE_B)

__global__ void __launch_bounds__(256, 1) gemm_tc_kernel(
    const __nv_bfloat16* __restrict__ aHp, const __nv_bfloat16* __restrict__ aLp,
    const __nv_bfloat16* __restrict__ wHp, const __nv_bfloat16* __restrict__ wLp,
    const float* __restrict__ bias, float* __restrict__ Out)
{
    extern __shared__ __align__(1024) char smem[];
    const uint32_t sb = smem_u32(smem);
    const int tid = threadIdx.x, lane = tid & 31, wid = tid >> 5;
    const int m0 = blockIdx.y * 128, n0 = blockIdx.x * 128;

    const int lr = tid >> 1;
    const int lc = (tid & 1) * 2;
    const int arow = m0 + lr;
    const uint32_t abytes = (arow < N_NODES) ? 16u : 0u;
    const size_t aoff = (size_t)(arow < N_NODES ? arow : 0) * D;
    const size_t woff = (size_t)(n0 + lr) * D;
    const uint32_t rb = (uint32_t)lr * 128;
    const uint32_t r7 = (uint32_t)(lr & 7);

    auto issue = [&](int ci, int s) {
        const int k0 = ci * 32;
        const __nv_bfloat16* pAH = aHp + aoff + k0;
        const __nv_bfloat16* pAL = aLp + aoff + k0;
        const __nv_bfloat16* pBH = wHp + woff + k0;
        const __nv_bfloat16* pBL = wLp + woff + k0;
        const uint32_t uA = sb + (uint32_t)s * STAGE_B;
        const uint32_t uB = uA + A_TILE;
#pragma unroll
        for (int j = 0; j < 2; j++) {
            const uint32_t c = (uint32_t)(lc + j);
            cp16(uA + rb + (((c    ) ^ r7) << 4), pAH + c * 8, abytes);
            cp16(uA + rb + (((c + 4) ^ r7) << 4), pAL + c * 8, abytes);
            cp16(uB + rb + (((c    ) ^ r7) << 4), pBH + c * 8, 16u);
            cp16(uB + rb + (((c + 4) ^ r7) << 4), pBL + c * 8, 16u);
        }
    };

    const int wm0 = (wid & 3) * 32, wn0 = (wid >> 2) * 64;
    const int af_r = lane & 15;
    const int af_c = lane >> 4;
    const int bf_r = (lane & 7) + ((lane >> 4) & 1) * 8;
    const int bf_c = (lane >> 3) & 1;

    float acc[2][8][4];
#pragma unroll
    for (int mi = 0; mi < 2; mi++)
#pragma unroll
        for (int nt = 0; nt < 8; nt++)
#pragma unroll
            for (int q = 0; q < 4; q++) acc[mi][nt][q] = 0.f;

    auto compute = [&](int s) {
        const uint32_t uA = sb + (uint32_t)s * STAGE_B;
        const uint32_t uB = uA + A_TILE;
#pragma unroll
        for (int ks = 0; ks < 2; ks++) {
            uint32_t ah[2][4], al[2][4], bb[4][4];
#pragma unroll
            for (int mi = 0; mi < 2; mi++) {
                int row = wm0 + mi * 16 + af_r;
                int c = ks * 2 + af_c;
                ldsm4(ah[mi], uA + row * 128 + (((c    ) ^ (row & 7)) << 4));
                ldsm4(al[mi], uA + row * 128 + (((c + 4) ^ (row & 7)) << 4));
            }
#pragma unroll
            for (int np = 0; np < 4; np++) {
                int row = wn0 + np * 16 + bf_r;
                int c = ks * 2 + bf_c;
                ldsm4(bb[np], uB + row * 128 + ((c ^ (row & 7)) << 4));
            }
#pragma unroll
            for (int mi = 0; mi < 2; mi++)
#pragma unroll
                for (int nt = 0; nt < 8; nt++)
                    mma16816(acc[mi][nt], ah[mi], &bb[nt >> 1][(nt & 1) * 2]);
#pragma unroll
            for (int mi = 0; mi < 2; mi++)
#pragma unroll
                for (int nt = 0; nt < 8; nt++)
                    mma16816(acc[mi][nt], al[mi], &bb[nt >> 1][(nt & 1) * 2]);
#pragma unroll
            for (int np = 0; np < 4; np++) {
                int row = wn0 + np * 16 + bf_r;
                int c = ks * 2 + bf_c + 4;
                ldsm4(bb[np], uB + row * 128 + ((c ^ (row & 7)) << 4));
            }
#pragma unroll
            for (int mi = 0; mi < 2; mi++)
#pragma unroll
                for (int nt = 0; nt < 8; nt++)
                    mma16816(acc[mi][nt], ah[mi], &bb[nt >> 1][(nt & 1) * 2]);
        }
    };

    for (int s = 0; s < NSTAGE - 1; s++) { issue(s, s); CP_COMMIT(); }
    for (int ci = 0; ci < N_CHUNK; ci++) {
        CP_WAIT2();
        __syncthreads();
        compute(ci & 3);
        if (ci + NSTAGE - 1 < N_CHUNK) issue(ci + NSTAGE - 1, (ci + NSTAGE - 1) & 3);
        CP_COMMIT();
    }

    const int er = lane >> 2, ec = (lane & 3) * 2;
    float bv[8][2];
#pragma unroll
    for (int nt = 0; nt < 8; nt++) {
        if (bias) {
            bv[nt][0] = __ldg(bias + n0 + wn0 + nt * 8 + ec);
            bv[nt][1] = __ldg(bias + n0 + wn0 + nt * 8 + ec + 1);
        } else { bv[nt][0] = 0.f; bv[nt][1] = 0.f; }
    }
#pragma unroll
    for (int mi = 0; mi < 2; mi++) {
        int r0 = m0 + wm0 + mi * 16 + er;
        if (r0 < N_NODES) {
            float* h0 = Out + (size_t)r0 * D + n0 + wn0 + ec;
#pragma unroll
            for (int nt = 0; nt < 8; nt++) {
                float2 o = make_float2(acc[mi][nt][0] + bv[nt][0],
                                       acc[mi][nt][1] + bv[nt][1]);
                *(float2*)(h0 + nt * 8) = o;
            }
        }
        int r1 = r0 + 8;
        if (r1 < N_NODES) {
            float* h1 = Out + (size_t)r1 * D + n0 + wn0 + ec;
#pragma unroll
            for (int nt = 0; nt < 8; nt++) {
                float2 o = make_float2(acc[mi][nt][2] + bv[nt][0],
                                       acc[mi][nt][3] + bv[nt][1]);
                *(float2*)(h1 + nt * 8) = o;
            }
        }
    }
}

// ---------------- LayerNorm(H1+H2) + ReLU + residual (+ fused split) --------
__global__ void __launch_bounds__(128) ln_kernel(
    const float* __restrict__ H1, const float* __restrict__ H2,
    const float* __restrict__ Xin,
    const float* __restrict__ gg, const float* __restrict__ bb,
    float* __restrict__ Xout,
    __nv_bfloat16* __restrict__ hi, __nv_bfloat16* __restrict__ lo)
{
    int row = blockIdx.x;
    int t = threadIdx.x;
    int lane = t & 31, wid = t >> 5;

    float4 va = ((const float4*)(H1 + (size_t)row * D))[t];
    float4 vb = ((const float4*)(H2 + (size_t)row * D))[t];
    float4 v = make_float4(va.x + vb.x, va.y + vb.y, va.z + vb.z, va.w + vb.w);
    float s  = v.x + v.y + v.z + v.w;
    float sq = v.x * v.x + v.y * v.y + v.z * v.z + v.w * v.w;

#pragma unroll
    for (int off = 16; off > 0; off >>= 1) {
        s  += __shfl_xor_sync(0xFFFFFFFFu, s,  off);
        sq += __shfl_xor_sync(0xFFFFFFFFu, sq, off);
    }
    __shared__ float ss[4], sqs[4];
    if (lane == 0) { ss[wid] = s; sqs[wid] = sq; }
    __syncthreads();
    s  = ss[0]  + ss[1]  + ss[2]  + ss[3];
    sq = sqs[0] + sqs[1] + sqs[2] + sqs[3];

    float mean = s * (1.0f / D);
    float var  = sq * (1.0f / D) - mean * mean;
    float rr   = rsqrtf(var + LN_EPS);

    float4 g4 = ((const float4*)gg)[t];
    float4 b4 = ((const float4*)bb)[t];
    float4 xi = ((const float4*)(Xin + (size_t)row * D))[t];

    float4 o;
    o.x = fmaxf((v.x - mean) * rr * g4.x + b4.x, 0.f) + xi.x;
    o.y = fmaxf((v.y - mean) * rr * g4.y + b4.y, 0.f) + xi.y;
    o.z = fmaxf((v.z - mean) * rr * g4.z + b4.z, 0.f) + xi.z;
    o.w = fmaxf((v.w - mean) * rr * g4.w + b4.w, 0.f) + xi.w;
    ((float4*)(Xout + (size_t)row * D))[t] = o;

    __nv_bfloat16 h0, h1, h2, h3, l0, l1, l2, l3;
    split2(o.x, h0, l0); split2(o.y, h1, l1);
    split2(o.z, h2, l2); split2(o.w, h3, l3);
    ((uint2*)(hi + (size_t)row * D))[t] = make_uint2(pk(h0, h1), pk(h2, h3));
    ((uint2*)(lo + (size_t)row * D))[t] = make_uint2(pk(l0, l1), pk(l2, l3));
}

// ---------------- launch ----------------------------------------------------
extern "C" void kernel_launch(void* const* d_in, const int* in_sizes, int n_in,
                              void* d_out, int out_size)
{
    const float* x   = (const float*)d_in[0];
    const int*   ei  = (const int*)  d_in[1];
    const float* Wl  = (const float*)d_in[2];
    const float* Wr  = (const float*)d_in[3];
    const float* b   = (const float*)d_in[4];
    const float* lng = (const float*)d_in[5];
    const float* lnb = (const float*)d_in[6];
    float* out = (float*)d_out;

    float *h1, *h2, *x0, *x1, *inv;
    int *deg, *rp, *cur, *bsum, *adj;
    __nv_bfloat16 *aH, *aL, *xH, *xL, *wlH, *wlL, *wrH, *wrL;
    cudaGetSymbolAddress((void**)&h1,   g_h1);
    cudaGetSymbolAddress((void**)&h2,   g_h2);
    cudaGetSymbolAddress((void**)&x0,   g_x0);
    cudaGetSymbolAddress((void**)&x1,   g_x1);
    cudaGetSymbolAddress((void**)&inv,  g_inv);
    cudaGetSymbolAddress((void**)&deg,  g_deg);
    cudaGetSymbolAddress((void**)&rp,   g_rp);
    cudaGetSymbolAddress((void**)&cur,  g_cur);
    cudaGetSymbolAddress((void**)&bsum, g_bsum);
    cudaGetSymbolAddress((void**)&adj,  g_adj);
    cudaGetSymbolAddress((void**)&aH,   g_aH);
    cudaGetSymbolAddress((void**)&aL,   g_aL);
    cudaGetSymbolAddress((void**)&xH,   g_xH);
    cudaGetSymbolAddress((void**)&xL,   g_xL);
    cudaGetSymbolAddress((void**)&wlH,  g_wlH);
    cudaGetSymbolAddress((void**)&wlL,  g_wlL);
    cudaGetSymbolAddress((void**)&wrH,  g_wrH);
    cudaGetSymbolAddress((void**)&wrL,  g_wrL);

    cudaFuncSetAttribute(gemm_tc_kernel,
                         cudaFuncAttributeMaxDynamicSharedMemorySize, GEMM_SMEM);

    cudaStream_t s2;
    cudaStreamCreateWithFlags(&s2, cudaStreamNonBlocking);
    cudaEvent_t evF[L_LAYERS], evJ[L_LAYERS];
    for (int l = 0; l < L_LAYERS; l++) {
        cudaEventCreateWithFlags(&evF[l], cudaEventDisableTiming);
        cudaEventCreateWithFlags(&evJ[l], cudaEventDisableTiming);
    }

    // ---- CSR build + pre-splits (serial on stream 0) ----
    zero_deg_kernel<<<(N_NODES + 255) / 256, 256>>>(deg);
    count_kernel<<<(N_EDGES + 255) / 256, 256>>>(ei, deg);
    scan1_kernel<<<SCAN_NBLK, SCAN_BS>>>(deg, rp, bsum);
    scan2_kernel<<<1, 256>>>(bsum);
    scan3_kernel<<<(N_NODES + 255) / 256, 256>>>(deg, rp, cur, inv, bsum);
    fill_kernel<<<(N_EDGES + 255) / 256, 256>>>(ei, cur, adj);

    split_kernel<<<N_NODES, 128>>>(x, xH, xL);
    split_kernel<<<L_LAYERS * D, 128>>>(Wl, wlH, wlL);
    split_kernel<<<L_LAYERS * D, 128>>>(Wr, wrH, wrL);

    const float* xin = x;
    float* outs[L_LAYERS] = { x0, x1, out };

    dim3 ggrid(D / 128, (N_NODES + 127) / 128);   // (4, 782)

    for (int l = 0; l < L_LAYERS; l++) {
        // fork: G2 = x @ Wr^T + bias on side stream (depends only on xH/xL)
        cudaEventRecord(evF[l], 0);
        cudaStreamWaitEvent(s2, evF[l], 0);
        gemm_tc_kernel<<<ggrid, 256, GEMM_SMEM, s2>>>(
            xH, xL, wrH + (size_t)l * D * D, wrL + (size_t)l * D * D,
            b + (size_t)l * D, h2);
        cudaEventRecord(evJ[l], s2);

        // main stream: aggregation then G1 = agg @ Wl^T
        agg_kernel<<<(N_NODES + 7) / 8, 256>>>(xin, rp, deg, inv, adj, aH, aL);
        gemm_tc_kernel<<<ggrid, 256, GEMM_SMEM>>>(
            aH, aL, wlH + (size_t)l * D * D, wlL + (size_t)l * D * D,
            nullptr, h1);

        // join, then LN(H1+H2) + ReLU + residual + split
        cudaStreamWaitEvent(0, evJ[l], 0);
        ln_kernel<<<N_NODES, 128>>>(h1, h2, xin, lng + (size_t)l * D,
                                    lnb + (size_t)l * D, outs[l], xH, xL);
        xin = outs[l];
    }

    for (int l = 0; l < L_LAYERS; l++) {
        cudaEventDestroy(evF[l]);
        cudaEventDestroy(evJ[l]);
    }
    cudaStreamDestroy(s2);
}

// round 10
// speedup vs baseline: 1.0278x; 1.0278x over previous
#include <cuda_runtime.h>
#include <cuda_bf16.h>
#include <cstdint>
#include <math.h>

#define N_NODES 100000
#define N_EDGES 819200
#define D 512
#define L_LAYERS 3
#define LN_EPS 1e-5f
#define SCAN_BS 512
#define SCAN_NBLK ((N_NODES + SCAN_BS - 1) / SCAN_BS)   // 196

#define N_MCHUNK 4
#define MBLK_TOTAL ((N_NODES + 127) / 128)              // 782
#define MBLK_PER_CHUNK ((MBLK_TOTAL + N_MCHUNK - 1) / N_MCHUNK)  // 196

// ---------------- scratch (static device globals; no allocation) ------------
__device__ float g_h  [(size_t)N_NODES * D];
__device__ float g_x0 [(size_t)N_NODES * D];
__device__ float g_x1 [(size_t)N_NODES * D];
__device__ float g_inv[N_NODES];
__device__ int   g_deg[N_NODES];
__device__ int   g_rp [N_NODES];
__device__ int   g_cur[N_NODES];
__device__ int   g_bsum[256];
__device__ int   g_adj[N_EDGES];
__device__ __align__(16) __nv_bfloat16 g_aH[(size_t)N_NODES * D];
__device__ __align__(16) __nv_bfloat16 g_aL[(size_t)N_NODES * D];
__device__ __align__(16) __nv_bfloat16 g_xH[(size_t)N_NODES * D];
__device__ __align__(16) __nv_bfloat16 g_xL[(size_t)N_NODES * D];
__device__ __align__(16) __nv_bfloat16 g_wlH[L_LAYERS * D * D];
__device__ __align__(16) __nv_bfloat16 g_wlL[L_LAYERS * D * D];
__device__ __align__(16) __nv_bfloat16 g_wrH[L_LAYERS * D * D];
__device__ __align__(16) __nv_bfloat16 g_wrL[L_LAYERS * D * D];

// ---------------- helpers ---------------------------------------------------
__device__ __forceinline__ uint32_t smem_u32(const void* p) {
    uint32_t a;
    asm("{ .reg .u64 t; cvta.to.shared.u64 t, %1; cvt.u32.u64 %0, t; }"
        : "=r"(a) : "l"(p));
    return a;
}
__device__ __forceinline__ uint32_t pk(__nv_bfloat16 a, __nv_bfloat16 b) {
    uint16_t ua = *(uint16_t*)&a, ub = *(uint16_t*)&b;
    return (uint32_t)ua | ((uint32_t)ub << 16);
}
__device__ __forceinline__ void ldsm4(uint32_t* r, uint32_t addr) {
    asm volatile("ldmatrix.sync.aligned.m8n8.x4.shared.b16 {%0,%1,%2,%3}, [%4];"
                 : "=r"(r[0]), "=r"(r[1]), "=r"(r[2]), "=r"(r[3]) : "r"(addr));
}
__device__ __forceinline__ void mma16816(float* c, const uint32_t* a, const uint32_t* b) {
    asm volatile("mma.sync.aligned.m16n8k16.row.col.f32.bf16.bf16.f32 "
                 "{%0,%1,%2,%3}, {%4,%5,%6,%7}, {%8,%9}, {%0,%1,%2,%3};"
                 : "+f"(c[0]), "+f"(c[1]), "+f"(c[2]), "+f"(c[3])
                 : "r"(a[0]), "r"(a[1]), "r"(a[2]), "r"(a[3]), "r"(b[0]), "r"(b[1]));
}
__device__ __forceinline__ void cp16(uint32_t dst, const void* src, uint32_t bytes) {
    asm volatile("cp.async.cg.shared.global [%0], [%1], 16, %2;"
                 :: "r"(dst), "l"(src), "r"(bytes) : "memory");
}
#define CP_COMMIT() asm volatile("cp.async.commit_group;" ::: "memory")
#define CP_WAIT2()  asm volatile("cp.async.wait_group 2;" ::: "memory")

__device__ __forceinline__ void split2(float v, __nv_bfloat16& h, __nv_bfloat16& l) {
    h = __float2bfloat16_rn(v);
    l = __float2bfloat16_rn(v - __bfloat162float(h));
}

// ---------------- CSR build -------------------------------------------------
__global__ void zero_deg_kernel(int* __restrict__ deg) {
    int i = blockIdx.x * blockDim.x + threadIdx.x;
    if (i < N_NODES) deg[i] = 0;
}
__global__ void count_kernel(const int* __restrict__ ei, int* __restrict__ deg) {
    int e = blockIdx.x * blockDim.x + threadIdx.x;
    if (e < N_EDGES) atomicAdd(&deg[ei[N_EDGES + e]], 1);
}
__global__ void __launch_bounds__(SCAN_BS) scan1_kernel(
    const int* __restrict__ deg, int* __restrict__ rp, int* __restrict__ bsum)
{
    __shared__ int sh[SCAN_BS];
    int t = threadIdx.x;
    int i = blockIdx.x * SCAN_BS + t;
    int v = (i < N_NODES) ? deg[i] : 0;
    sh[t] = v; __syncthreads();
    for (int off = 1; off < SCAN_BS; off <<= 1) {
        int u = (t >= off) ? sh[t - off] : 0;
        __syncthreads();
        sh[t] += u;
        __syncthreads();
    }
    if (i < N_NODES) rp[i] = sh[t] - v;
    if (t == SCAN_BS - 1) bsum[blockIdx.x] = sh[t];
}
__global__ void __launch_bounds__(256) scan2_kernel(int* __restrict__ bsum) {
    __shared__ int sh[256];
    int t = threadIdx.x;
    int v = (t < SCAN_NBLK) ? bsum[t] : 0;
    sh[t] = v; __syncthreads();
    for (int off = 1; off < 256; off <<= 1) {
        int u = (t >= off) ? sh[t - off] : 0;
        __syncthreads();
        sh[t] += u;
        __syncthreads();
    }
    if (t < SCAN_NBLK) bsum[t] = sh[t] - v;
}
__global__ void scan3_kernel(const int* __restrict__ deg, int* __restrict__ rp,
                             int* __restrict__ cur, float* __restrict__ inv,
                             const int* __restrict__ bsum)
{
    int i = blockIdx.x * blockDim.x + threadIdx.x;
    if (i < N_NODES) {
        int r = rp[i] + bsum[i >> 9];
        rp[i] = r;
        cur[i] = r;
        inv[i] = 1.0f / (float)max(deg[i], 1);
    }
}
__global__ void fill_kernel(const int* __restrict__ ei, int* __restrict__ cur,
                            int* __restrict__ adj)
{
    int e = blockIdx.x * blockDim.x + threadIdx.x;
    if (e < N_EDGES) {
        int slot = atomicAdd(&cur[ei[N_EDGES + e]], 1);
        adj[slot] = ei[e];
    }
}

// ---------------- CSR gather aggregation + mean + bf16 split (node range) ---
__global__ void __launch_bounds__(256) agg_kernel(
    const float* __restrict__ x, const int* __restrict__ rp,
    const int* __restrict__ deg, const float* __restrict__ inv,
    const int* __restrict__ adj,
    __nv_bfloat16* __restrict__ hi, __nv_bfloat16* __restrict__ lo,
    int node0, int node1)
{
    int node = node0 + blockIdx.x * 8 + (threadIdx.x >> 5);
    if (node >= node1) return;
    int lane = threadIdx.x & 31;

    float4 acc[4];
#pragma unroll
    for (int q = 0; q < 4; q++) acc[q] = make_float4(0.f, 0.f, 0.f, 0.f);

    int beg = __ldg(&rp[node]);
    int d   = __ldg(&deg[node]);
    int j = 0;
    for (; j + 2 <= d; j += 2) {
        int s0 = __ldg(&adj[beg + j]);
        int s1 = __ldg(&adj[beg + j + 1]);
        const float4* r0 = (const float4*)(x + (size_t)s0 * D);
        const float4* r1 = (const float4*)(x + (size_t)s1 * D);
        float4 v0[4], v1[4];
#pragma unroll
        for (int q = 0; q < 4; q++) v0[q] = __ldg(r0 + lane + q * 32);
#pragma unroll
        for (int q = 0; q < 4; q++) v1[q] = __ldg(r1 + lane + q * 32);
#pragma unroll
        for (int q = 0; q < 4; q++) {
            acc[q].x += v0[q].x + v1[q].x;
            acc[q].y += v0[q].y + v1[q].y;
            acc[q].z += v0[q].z + v1[q].z;
            acc[q].w += v0[q].w + v1[q].w;
        }
    }
    if (j < d) {
        int s0 = __ldg(&adj[beg + j]);
        const float4* r0 = (const float4*)(x + (size_t)s0 * D);
#pragma unroll
        for (int q = 0; q < 4; q++) {
            float4 v = __ldg(r0 + lane + q * 32);
            acc[q].x += v.x; acc[q].y += v.y; acc[q].z += v.z; acc[q].w += v.w;
        }
    }
    float s = __ldg(&inv[node]);
    uint2* ph = (uint2*)(hi + (size_t)node * D);
    uint2* pl = (uint2*)(lo + (size_t)node * D);
#pragma unroll
    for (int q = 0; q < 4; q++) {
        float4 v = acc[q];
        v.x *= s; v.y *= s; v.z *= s; v.w *= s;
        __nv_bfloat16 h0, h1, h2, h3, l0, l1, l2, l3;
        split2(v.x, h0, l0); split2(v.y, h1, l1);
        split2(v.z, h2, l2); split2(v.w, h3, l3);
        ph[lane + q * 32] = make_uint2(pk(h0, h1), pk(h2, h3));
        pl[lane + q * 32] = make_uint2(pk(l0, l1), pk(l2, l3));
    }
}

// ---------------- fp32 -> (bf16 hi, bf16 lo) split --------------------------
__global__ void __launch_bounds__(128) split_kernel(
    const float* __restrict__ in,
    __nv_bfloat16* __restrict__ hi, __nv_bfloat16* __restrict__ lo)
{
    size_t row = blockIdx.x;
    int t = threadIdx.x;
    float4 v = ((const float4*)(in + row * D))[t];
    __nv_bfloat16 h0, h1, h2, h3, l0, l1, l2, l3;
    split2(v.x, h0, l0); split2(v.y, h1, l1);
    split2(v.z, h2, l2); split2(v.w, h3, l3);
    ((uint2*)(hi + row * D))[t] = make_uint2(pk(h0, h1), pk(h2, h3));
    ((uint2*)(lo + row * D))[t] = make_uint2(pk(l0, l1), pk(l2, l3));
}

// ---------------- fused bf16-split tensor-core GEMM (K=1024, M-chunked) -----
// H[m, n0:+128] = agg@Wl^T + x@Wr^T + bias for m in this chunk's rows
#define NSTAGE 4
#define A_TILE 16384
#define STAGE_B 32768
#define GEMM_SMEM (NSTAGE * STAGE_B)

__global__ void __launch_bounds__(256, 1) gemm_tc_kernel(
    const __nv_bfloat16* __restrict__ aH, const __nv_bfloat16* __restrict__ aL,
    const __nv_bfloat16* __restrict__ xH, const __nv_bfloat16* __restrict__ xL,
    const __nv_bfloat16* __restrict__ wlH, const __nv_bfloat16* __restrict__ wlL,
    const __nv_bfloat16* __restrict__ wrH, const __nv_bfloat16* __restrict__ wrL,
    const float* __restrict__ bias, float* __restrict__ H, int mblk0)
{
    extern __shared__ __align__(1024) char smem[];
    const uint32_t sb = smem_u32(smem);
    const int tid = threadIdx.x, lane = tid & 31, wid = tid >> 5;
    const int m0 = (mblk0 + blockIdx.y) * 128, n0 = blockIdx.x * 128;

    const int lr = tid >> 1;
    const int lc = (tid & 1) * 2;
    const int arow = m0 + lr;
    const uint32_t abytes = (arow < N_NODES) ? 16u : 0u;
    const size_t aoff = (size_t)(arow < N_NODES ? arow : 0) * D;
    const size_t woff = (size_t)(n0 + lr) * D;
    const uint32_t rb = (uint32_t)lr * 128;
    const uint32_t r7 = (uint32_t)(lr & 7);

    auto issue = [&](int ci, int s) {
        const int ph = ci >> 4;
        const int k0 = (ci & 15) * 32;
        const __nv_bfloat16* pAH = (ph ? xH : aH) + aoff + k0;
        const __nv_bfloat16* pAL = (ph ? xL : aL) + aoff + k0;
        const __nv_bfloat16* pBH = (ph ? wrH : wlH) + woff + k0;
        const __nv_bfloat16* pBL = (ph ? wrL : wlL) + woff + k0;
        const uint32_t uA = sb + (uint32_t)s * STAGE_B;
        const uint32_t uB = uA + A_TILE;
#pragma unroll
        for (int j = 0; j < 2; j++) {
            const uint32_t c = (uint32_t)(lc + j);
            cp16(uA + rb + (((c    ) ^ r7) << 4), pAH + c * 8, abytes);
            cp16(uA + rb + (((c + 4) ^ r7) << 4), pAL + c * 8, abytes);
            cp16(uB + rb + (((c    ) ^ r7) << 4), pBH + c * 8, 16u);
            cp16(uB + rb + (((c + 4) ^ r7) << 4), pBL + c * 8, 16u);
        }
    };

    const int wm0 = (wid & 3) * 32, wn0 = (wid >> 2) * 64;
    const int af_r = lane & 15;
    const int af_c = lane >> 4;
    const int bf_r = (lane & 7) + ((lane >> 4) & 1) * 8;
    const int bf_c = (lane >> 3) & 1;

    float acc[2][8][4];
#pragma unroll
    for (int mi = 0; mi < 2; mi++)
#pragma unroll
        for (int nt = 0; nt < 8; nt++)
#pragma unroll
            for (int q = 0; q < 4; q++) acc[mi][nt][q] = 0.f;

    auto compute = [&](int s) {
        const uint32_t uA = sb + (uint32_t)s * STAGE_B;
        const uint32_t uB = uA + A_TILE;
#pragma unroll
        for (int ks = 0; ks < 2; ks++) {
            uint32_t ah[2][4], al[2][4], bb[4][4];
#pragma unroll
            for (int mi = 0; mi < 2; mi++) {
                int row = wm0 + mi * 16 + af_r;
                int c = ks * 2 + af_c;
                ldsm4(ah[mi], uA + row * 128 + (((c    ) ^ (row & 7)) << 4));
                ldsm4(al[mi], uA + row * 128 + (((c + 4) ^ (row & 7)) << 4));
            }
#pragma unroll
            for (int np = 0; np < 4; np++) {
                int row = wn0 + np * 16 + bf_r;
                int c = ks * 2 + bf_c;
                ldsm4(bb[np], uB + row * 128 + ((c ^ (row & 7)) << 4));
            }
#pragma unroll
            for (int mi = 0; mi < 2; mi++)
#pragma unroll
                for (int nt = 0; nt < 8; nt++)
                    mma16816(acc[mi][nt], ah[mi], &bb[nt >> 1][(nt & 1) * 2]);
#pragma unroll
            for (int mi = 0; mi < 2; mi++)
#pragma unroll
                for (int nt = 0; nt < 8; nt++)
                    mma16816(acc[mi][nt], al[mi], &bb[nt >> 1][(nt & 1) * 2]);
#pragma unroll
            for (int np = 0; np < 4; np++) {
                int row = wn0 + np * 16 + bf_r;
                int c = ks * 2 + bf_c + 4;
                ldsm4(bb[np], uB + row * 128 + ((c ^ (row & 7)) << 4));
            }
#pragma unroll
            for (int mi = 0; mi < 2; mi++)
#pragma unroll
                for (int nt = 0; nt < 8; nt++)
                    mma16816(acc[mi][nt], ah[mi], &bb[nt >> 1][(nt & 1) * 2]);
        }
    };

    for (int s = 0; s < NSTAGE - 1; s++) { issue(s, s); CP_COMMIT(); }
    for (int ci = 0; ci < 32; ci++) {
        CP_WAIT2();
        __syncthreads();
        compute(ci & 3);
        if (ci + NSTAGE - 1 < 32) issue(ci + NSTAGE - 1, (ci + NSTAGE - 1) & 3);
        CP_COMMIT();
    }

    const int er = lane >> 2, ec = (lane & 3) * 2;
    float bv[8][2];
#pragma unroll
    for (int nt = 0; nt < 8; nt++) {
        bv[nt][0] = __ldg(bias + n0 + wn0 + nt * 8 + ec);
        bv[nt][1] = __ldg(bias + n0 + wn0 + nt * 8 + ec + 1);
    }
#pragma unroll
    for (int mi = 0; mi < 2; mi++) {
        int r0 = m0 + wm0 + mi * 16 + er;
        if (r0 < N_NODES) {
            float* h0 = H + (size_t)r0 * D + n0 + wn0 + ec;
#pragma unroll
            for (int nt = 0; nt < 8; nt++) {
                float2 o = make_float2(acc[mi][nt][0] + bv[nt][0],
                                       acc[mi][nt][1] + bv[nt][1]);
                *(float2*)(h0 + nt * 8) = o;
            }
        }
        int r1 = r0 + 8;
        if (r1 < N_NODES) {
            float* h1 = H + (size_t)r1 * D + n0 + wn0 + ec;
#pragma unroll
            for (int nt = 0; nt < 8; nt++) {
                float2 o = make_float2(acc[mi][nt][2] + bv[nt][0],
                                       acc[mi][nt][3] + bv[nt][1]);
                *(float2*)(h1 + nt * 8) = o;
            }
        }
    }
}

// ---------------- LayerNorm + ReLU + residual (+ fused split, row offset) ---
__global__ void __launch_bounds__(128) ln_kernel(
    const float* __restrict__ H, const float* __restrict__ Xin,
    const float* __restrict__ gg, const float* __restrict__ bb,
    float* __restrict__ Xout,
    __nv_bfloat16* __restrict__ hi, __nv_bfloat16* __restrict__ lo, int row0)
{
    int row = row0 + blockIdx.x;
    int t = threadIdx.x;
    int lane = t & 31, wid = t >> 5;

    float4 v = ((const float4*)(H + (size_t)row * D))[t];
    float s  = v.x + v.y + v.z + v.w;
    float sq = v.x * v.x + v.y * v.y + v.z * v.z + v.w * v.w;

#pragma unroll
    for (int off = 16; off > 0; off >>= 1) {
        s  += __shfl_xor_sync(0xFFFFFFFFu, s,  off);
        sq += __shfl_xor_sync(0xFFFFFFFFu, sq, off);
    }
    __shared__ float ss[4], sqs[4];
    if (lane == 0) { ss[wid] = s; sqs[wid] = sq; }
    __syncthreads();
    s  = ss[0]  + ss[1]  + ss[2]  + ss[3];
    sq = sqs[0] + sqs[1] + sqs[2] + sqs[3];

    float mean = s * (1.0f / D);
    float var  = sq * (1.0f / D) - mean * mean;
    float rr   = rsqrtf(var + LN_EPS);

    float4 g4 = ((const float4*)gg)[t];
    float4 b4 = ((const float4*)bb)[t];
    float4 xi = ((const float4*)(Xin + (size_t)row * D))[t];

    float4 o;
    o.x = fmaxf((v.x - mean) * rr * g4.x + b4.x, 0.f) + xi.x;
    o.y = fmaxf((v.y - mean) * rr * g4.y + b4.y, 0.f) + xi.y;
    o.z = fmaxf((v.z - mean) * rr * g4.z + b4.z, 0.f) + xi.z;
    o.w = fmaxf((v.w - mean) * rr * g4.w + b4.w, 0.f) + xi.w;
    ((float4*)(Xout + (size_t)row * D))[t] = o;

    __nv_bfloat16 h0, h1, h2, h3, l0, l1, l2, l3;
    split2(o.x, h0, l0); split2(o.y, h1, l1);
    split2(o.z, h2, l2); split2(o.w, h3, l3);
    ((uint2*)(hi + (size_t)row * D))[t] = make_uint2(pk(h0, h1), pk(h2, h3));
    ((uint2*)(lo + (size_t)row * D))[t] = make_uint2(pk(l0, l1), pk(l2, l3));
}

// ---------------- launch ----------------------------------------------------
extern "C" void kernel_launch(void* const* d_in, const int* in_sizes, int n_in,
                              void* d_out, int out_size)
{
    const float* x   = (const float*)d_in[0];
    const int*   ei  = (const int*)  d_in[1];
    const float* Wl  = (const float*)d_in[2];
    const float* Wr  = (const float*)d_in[3];
    const float* b   = (const float*)d_in[4];
    const float* lng = (const float*)d_in[5];
    const float* lnb = (const float*)d_in[6];
    float* out = (float*)d_out;

    float *h, *x0, *x1, *inv;
    int *deg, *rp, *cur, *bsum, *adj;
    __nv_bfloat16 *aH, *aL, *xH, *xL, *wlH, *wlL, *wrH, *wrL;
    cudaGetSymbolAddress((void**)&h,    g_h);
    cudaGetSymbolAddress((void**)&x0,   g_x0);
    cudaGetSymbolAddress((void**)&x1,   g_x1);
    cudaGetSymbolAddress((void**)&inv,  g_inv);
    cudaGetSymbolAddress((void**)&deg,  g_deg);
    cudaGetSymbolAddress((void**)&rp,   g_rp);
    cudaGetSymbolAddress((void**)&cur,  g_cur);
    cudaGetSymbolAddress((void**)&bsum, g_bsum);
    cudaGetSymbolAddress((void**)&adj,  g_adj);
    cudaGetSymbolAddress((void**)&aH,   g_aH);
    cudaGetSymbolAddress((void**)&aL,   g_aL);
    cudaGetSymbolAddress((void**)&xH,   g_xH);
    cudaGetSymbolAddress((void**)&xL,   g_xL);
    cudaGetSymbolAddress((void**)&wlH,  g_wlH);
    cudaGetSymbolAddress((void**)&wlL,  g_wlL);
    cudaGetSymbolAddress((void**)&wrH,  g_wrH);
    cudaGetSymbolAddress((void**)&wrL,  g_wrL);

    cudaFuncSetAttribute(gemm_tc_kernel,
                         cudaFuncAttributeMaxDynamicSharedMemorySize, GEMM_SMEM);

    cudaStream_t s2;
    cudaStreamCreateWithFlags(&s2, cudaStreamNonBlocking);
    cudaEvent_t evA[L_LAYERS][N_MCHUNK], evG[L_LAYERS][N_MCHUNK];
    for (int l = 0; l < L_LAYERS; l++)
        for (int c = 0; c < N_MCHUNK; c++) {
            cudaEventCreateWithFlags(&evA[l][c], cudaEventDisableTiming);
            cudaEventCreateWithFlags(&evG[l][c], cudaEventDisableTiming);
        }

    // ---- CSR build + pre-splits (serial on stream 0) ----
    zero_deg_kernel<<<(N_NODES + 255) / 256, 256>>>(deg);
    count_kernel<<<(N_EDGES + 255) / 256, 256>>>(ei, deg);
    scan1_kernel<<<SCAN_NBLK, SCAN_BS>>>(deg, rp, bsum);
    scan2_kernel<<<1, 256>>>(bsum);
    scan3_kernel<<<(N_NODES + 255) / 256, 256>>>(deg, rp, cur, inv, bsum);
    fill_kernel<<<(N_EDGES + 255) / 256, 256>>>(ei, cur, adj);

    split_kernel<<<N_NODES, 128>>>(x, xH, xL);
    split_kernel<<<L_LAYERS * D, 128>>>(Wl, wlH, wlL);
    split_kernel<<<L_LAYERS * D, 128>>>(Wr, wrH, wrL);

    const float* xin = x;
    float* outs[L_LAYERS] = { x0, x1, out };

    for (int l = 0; l < L_LAYERS; l++) {
        // chunk geometry
        int mblk0[N_MCHUNK], nmblk[N_MCHUNK], nd0[N_MCHUNK], nd1[N_MCHUNK];
        for (int c = 0; c < N_MCHUNK; c++) {
            mblk0[c] = c * MBLK_PER_CHUNK;
            int e = mblk0[c] + MBLK_PER_CHUNK;
            if (e > MBLK_TOTAL) e = MBLK_TOTAL;
            nmblk[c] = e - mblk0[c];
            nd0[c] = mblk0[c] * 128;
            nd1[c] = e * 128; if (nd1[c] > N_NODES) nd1[c] = N_NODES;
        }

        // main stream: agg chunks (record events as each finishes)
        for (int c = 0; c < N_MCHUNK; c++) {
            int nnodes = nd1[c] - nd0[c];
            agg_kernel<<<(nnodes + 7) / 8, 256>>>(xin, rp, deg, inv, adj,
                                                  aH, aL, nd0[c], nd1[c]);
            cudaEventRecord(evA[l][c], 0);
        }
        // s2: gemm chunk fires as soon as its agg lands
        for (int c = 0; c < N_MCHUNK; c++) {
            cudaStreamWaitEvent(s2, evA[l][c], 0);
            dim3 g(D / 128, nmblk[c]);
            gemm_tc_kernel<<<g, 256, GEMM_SMEM, s2>>>(
                aH, aL, xH, xL,
                wlH + (size_t)l * D * D, wlL + (size_t)l * D * D,
                wrH + (size_t)l * D * D, wrL + (size_t)l * D * D,
                b + (size_t)l * D, h, mblk0[c]);
            cudaEventRecord(evG[l][c], s2);
        }
        // main stream: ln chunks after their gemm
        for (int c = 0; c < N_MCHUNK; c++) {
            cudaStreamWaitEvent(0, evG[l][c], 0);
            int nnodes = nd1[c] - nd0[c];
            ln_kernel<<<nnodes, 128>>>(h, xin, lng + (size_t)l * D,
                                       lnb + (size_t)l * D, outs[l],
                                       xH, xL, nd0[c]);
        }
        xin = outs[l];
    }

    for (int l = 0; l < L_LAYERS; l++)
        for (int c = 0; c < N_MCHUNK; c++) {
            cudaEventDestroy(evA[l][c]);
            cudaEventDestroy(evG[l][c]);
        }
    cudaStreamDestroy(s2);
}

// round 11
// speedup vs baseline: 1.1502x; 1.1190x over previous
#include <cuda_runtime.h>
#include <cuda_bf16.h>
#include <cstdint>
#include <math.h>

#define N_NODES 100000
#define N_EDGES 819200
#define D 512
#define L_LAYERS 3
#define LN_EPS 1e-5f
#define SCAN_BS 512
#define SCAN_NBLK ((N_NODES + SCAN_BS - 1) / SCAN_BS)   // 196

#define N_MCHUNK 4
#define MBLK_TOTAL ((N_NODES + 127) / 128)              // 782
#define MBLK_PER_CHUNK ((MBLK_TOTAL + N_MCHUNK - 1) / N_MCHUNK)  // 196

// ---------------- scratch (static device globals; no allocation) ------------
__device__ float g_h  [(size_t)N_NODES * D];
__device__ float g_x0 [(size_t)N_NODES * D];
__device__ float g_x1 [(size_t)N_NODES * D];
__device__ float g_inv[N_NODES];
__device__ int   g_deg[N_NODES];
__device__ int   g_rp [N_NODES];
__device__ int   g_cur[N_NODES];
__device__ int   g_bsum[256];
__device__ int   g_adj[N_EDGES];
__device__ __align__(16) __nv_bfloat16 g_aH[(size_t)N_NODES * D];
__device__ __align__(16) __nv_bfloat16 g_aL[(size_t)N_NODES * D];
__device__ __align__(16) __nv_bfloat16 g_xH[(size_t)N_NODES * D];
__device__ __align__(16) __nv_bfloat16 g_xL[(size_t)N_NODES * D];
__device__ __align__(16) __nv_bfloat16 g_wlH[L_LAYERS * D * D];
__device__ __align__(16) __nv_bfloat16 g_wlL[L_LAYERS * D * D];
__device__ __align__(16) __nv_bfloat16 g_wrH[L_LAYERS * D * D];
__device__ __align__(16) __nv_bfloat16 g_wrL[L_LAYERS * D * D];

// ---------------- helpers ---------------------------------------------------
__device__ __forceinline__ uint32_t smem_u32(const void* p) {
    uint32_t a;
    asm("{ .reg .u64 t; cvta.to.shared.u64 t, %1; cvt.u32.u64 %0, t; }"
        : "=r"(a) : "l"(p));
    return a;
}
__device__ __forceinline__ uint32_t pk(__nv_bfloat16 a, __nv_bfloat16 b) {
    uint16_t ua = *(uint16_t*)&a, ub = *(uint16_t*)&b;
    return (uint32_t)ua | ((uint32_t)ub << 16);
}
__device__ __forceinline__ void ldsm4(uint32_t* r, uint32_t addr) {
    asm volatile("ldmatrix.sync.aligned.m8n8.x4.shared.b16 {%0,%1,%2,%3}, [%4];"
                 : "=r"(r[0]), "=r"(r[1]), "=r"(r[2]), "=r"(r[3]) : "r"(addr));
}
__device__ __forceinline__ void mma16816(float* c, const uint32_t* a, const uint32_t* b) {
    asm volatile("mma.sync.aligned.m16n8k16.row.col.f32.bf16.bf16.f32 "
                 "{%0,%1,%2,%3}, {%4,%5,%6,%7}, {%8,%9}, {%0,%1,%2,%3};"
                 : "+f"(c[0]), "+f"(c[1]), "+f"(c[2]), "+f"(c[3])
                 : "r"(a[0]), "r"(a[1]), "r"(a[2]), "r"(a[3]), "r"(b[0]), "r"(b[1]));
}
__device__ __forceinline__ void cp16(uint32_t dst, const void* src, uint32_t bytes) {
    asm volatile("cp.async.cg.shared.global [%0], [%1], 16, %2;"
                 :: "r"(dst), "l"(src), "r"(bytes) : "memory");
}
#define CP_COMMIT() asm volatile("cp.async.commit_group;" ::: "memory")
#define CP_WAIT1()  asm volatile("cp.async.wait_group 1;" ::: "memory")

__device__ __forceinline__ void split2(float v, __nv_bfloat16& h, __nv_bfloat16& l) {
    h = __float2bfloat16_rn(v);
    l = __float2bfloat16_rn(v - __bfloat162float(h));
}

// ---------------- CSR build -------------------------------------------------
__global__ void zero_deg_kernel(int* __restrict__ deg) {
    int i = blockIdx.x * blockDim.x + threadIdx.x;
    if (i < N_NODES) deg[i] = 0;
}
__global__ void count_kernel(const int* __restrict__ ei, int* __restrict__ deg) {
    int e = blockIdx.x * blockDim.x + threadIdx.x;
    if (e < N_EDGES) atomicAdd(&deg[ei[N_EDGES + e]], 1);
}
__global__ void __launch_bounds__(SCAN_BS) scan1_kernel(
    const int* __restrict__ deg, int* __restrict__ rp, int* __restrict__ bsum)
{
    __shared__ int sh[SCAN_BS];
    int t = threadIdx.x;
    int i = blockIdx.x * SCAN_BS + t;
    int v = (i < N_NODES) ? deg[i] : 0;
    sh[t] = v; __syncthreads();
    for (int off = 1; off < SCAN_BS; off <<= 1) {
        int u = (t >= off) ? sh[t - off] : 0;
        __syncthreads();
        sh[t] += u;
        __syncthreads();
    }
    if (i < N_NODES) rp[i] = sh[t] - v;
    if (t == SCAN_BS - 1) bsum[blockIdx.x] = sh[t];
}
__global__ void __launch_bounds__(256) scan2_kernel(int* __restrict__ bsum) {
    __shared__ int sh[256];
    int t = threadIdx.x;
    int v = (t < SCAN_NBLK) ? bsum[t] : 0;
    sh[t] = v; __syncthreads();
    for (int off = 1; off < 256; off <<= 1) {
        int u = (t >= off) ? sh[t - off] : 0;
        __syncthreads();
        sh[t] += u;
        __syncthreads();
    }
    if (t < SCAN_NBLK) bsum[t] = sh[t] - v;
}
__global__ void scan3_kernel(const int* __restrict__ deg, int* __restrict__ rp,
                             int* __restrict__ cur, float* __restrict__ inv,
                             const int* __restrict__ bsum)
{
    int i = blockIdx.x * blockDim.x + threadIdx.x;
    if (i < N_NODES) {
        int r = rp[i] + bsum[i >> 9];
        rp[i] = r;
        cur[i] = r;
        inv[i] = 1.0f / (float)max(deg[i], 1);
    }
}
__global__ void fill_kernel(const int* __restrict__ ei, int* __restrict__ cur,
                            int* __restrict__ adj)
{
    int e = blockIdx.x * blockDim.x + threadIdx.x;
    if (e < N_EDGES) {
        int slot = atomicAdd(&cur[ei[N_EDGES + e]], 1);
        adj[slot] = ei[e];
    }
}

// ---------------- CSR gather aggregation + mean + bf16 split (node range) ---
__global__ void __launch_bounds__(256) agg_kernel(
    const float* __restrict__ x, const int* __restrict__ rp,
    const int* __restrict__ deg, const float* __restrict__ inv,
    const int* __restrict__ adj,
    __nv_bfloat16* __restrict__ hi, __nv_bfloat16* __restrict__ lo,
    int node0, int node1)
{
    int node = node0 + blockIdx.x * 8 + (threadIdx.x >> 5);
    if (node >= node1) return;
    int lane = threadIdx.x & 31;

    float4 acc[4];
#pragma unroll
    for (int q = 0; q < 4; q++) acc[q] = make_float4(0.f, 0.f, 0.f, 0.f);

    int beg = __ldg(&rp[node]);
    int d   = __ldg(&deg[node]);
    int j = 0;
    for (; j + 2 <= d; j += 2) {
        int s0 = __ldg(&adj[beg + j]);
        int s1 = __ldg(&adj[beg + j + 1]);
        const float4* r0 = (const float4*)(x + (size_t)s0 * D);
        const float4* r1 = (const float4*)(x + (size_t)s1 * D);
        float4 v0[4], v1[4];
#pragma unroll
        for (int q = 0; q < 4; q++) v0[q] = __ldg(r0 + lane + q * 32);
#pragma unroll
        for (int q = 0; q < 4; q++) v1[q] = __ldg(r1 + lane + q * 32);
#pragma unroll
        for (int q = 0; q < 4; q++) {
            acc[q].x += v0[q].x + v1[q].x;
            acc[q].y += v0[q].y + v1[q].y;
            acc[q].z += v0[q].z + v1[q].z;
            acc[q].w += v0[q].w + v1[q].w;
        }
    }
    if (j < d) {
        int s0 = __ldg(&adj[beg + j]);
        const float4* r0 = (const float4*)(x + (size_t)s0 * D);
#pragma unroll
        for (int q = 0; q < 4; q++) {
            float4 v = __ldg(r0 + lane + q * 32);
            acc[q].x += v.x; acc[q].y += v.y; acc[q].z += v.z; acc[q].w += v.w;
        }
    }
    float s = __ldg(&inv[node]);
    uint2* ph = (uint2*)(hi + (size_t)node * D);
    uint2* pl = (uint2*)(lo + (size_t)node * D);
#pragma unroll
    for (int q = 0; q < 4; q++) {
        float4 v = acc[q];
        v.x *= s; v.y *= s; v.z *= s; v.w *= s;
        __nv_bfloat16 h0, h1, h2, h3, l0, l1, l2, l3;
        split2(v.x, h0, l0); split2(v.y, h1, l1);
        split2(v.z, h2, l2); split2(v.w, h3, l3);
        ph[lane + q * 32] = make_uint2(pk(h0, h1), pk(h2, h3));
        pl[lane + q * 32] = make_uint2(pk(l0, l1), pk(l2, l3));
    }
}

// ---------------- fp32 -> (bf16 hi, bf16 lo) split --------------------------
__global__ void __launch_bounds__(128) split_kernel(
    const float* __restrict__ in,
    __nv_bfloat16* __restrict__ hi, __nv_bfloat16* __restrict__ lo)
{
    size_t row = blockIdx.x;
    int t = threadIdx.x;
    float4 v = ((const float4*)(in + row * D))[t];
    __nv_bfloat16 h0, h1, h2, h3, l0, l1, l2, l3;
    split2(v.x, h0, l0); split2(v.y, h1, l1);
    split2(v.z, h2, l2); split2(v.w, h3, l3);
    ((uint2*)(hi + row * D))[t] = make_uint2(pk(h0, h1), pk(h2, h3));
    ((uint2*)(lo + row * D))[t] = make_uint2(pk(l0, l1), pk(l2, l3));
}

// ---------------- fused bf16-split tensor-core GEMM (K=1024, M-chunked) -----
// 3-stage pipeline, 96KB smem/CTA -> 2 CTAs/SM (16 warps) for latency hiding
// and co-residency with the DRAM-bound agg kernel.
#define NSTAGE 3
#define A_TILE 16384
#define STAGE_B 32768
#define GEMM_SMEM (NSTAGE * STAGE_B)

__global__ void __launch_bounds__(256, 2) gemm_tc_kernel(
    const __nv_bfloat16* __restrict__ aH, const __nv_bfloat16* __restrict__ aL,
    const __nv_bfloat16* __restrict__ xH, const __nv_bfloat16* __restrict__ xL,
    const __nv_bfloat16* __restrict__ wlH, const __nv_bfloat16* __restrict__ wlL,
    const __nv_bfloat16* __restrict__ wrH, const __nv_bfloat16* __restrict__ wrL,
    const float* __restrict__ bias, float* __restrict__ H, int mblk0)
{
    extern __shared__ __align__(1024) char smem[];
    const uint32_t sb = smem_u32(smem);
    const int tid = threadIdx.x, lane = tid & 31, wid = tid >> 5;
    const int m0 = (mblk0 + blockIdx.y) * 128, n0 = blockIdx.x * 128;

    const int lr = tid >> 1;
    const int lc = (tid & 1) * 2;
    const int arow = m0 + lr;
    const uint32_t abytes = (arow < N_NODES) ? 16u : 0u;
    const size_t aoff = (size_t)(arow < N_NODES ? arow : 0) * D;
    const size_t woff = (size_t)(n0 + lr) * D;
    const uint32_t rb = (uint32_t)lr * 128;
    const uint32_t r7 = (uint32_t)(lr & 7);

    auto issue = [&](int ci, int s) {
        const int ph = ci >> 4;
        const int k0 = (ci & 15) * 32;
        const __nv_bfloat16* pAH = (ph ? xH : aH) + aoff + k0;
        const __nv_bfloat16* pAL = (ph ? xL : aL) + aoff + k0;
        const __nv_bfloat16* pBH = (ph ? wrH : wlH) + woff + k0;
        const __nv_bfloat16* pBL = (ph ? wrL : wlL) + woff + k0;
        const uint32_t uA = sb + (uint32_t)s * STAGE_B;
        const uint32_t uB = uA + A_TILE;
#pragma unroll
        for (int j = 0; j < 2; j++) {
            const uint32_t c = (uint32_t)(lc + j);
            cp16(uA + rb + (((c    ) ^ r7) << 4), pAH + c * 8, abytes);
            cp16(uA + rb + (((c + 4) ^ r7) << 4), pAL + c * 8, abytes);
            cp16(uB + rb + (((c    ) ^ r7) << 4), pBH + c * 8, 16u);
            cp16(uB + rb + (((c + 4) ^ r7) << 4), pBL + c * 8, 16u);
        }
    };

    const int wm0 = (wid & 3) * 32, wn0 = (wid >> 2) * 64;
    const int af_r = lane & 15;
    const int af_c = lane >> 4;
    const int bf_r = (lane & 7) + ((lane >> 4) & 1) * 8;
    const int bf_c = (lane >> 3) & 1;

    float acc[2][8][4];
#pragma unroll
    for (int mi = 0; mi < 2; mi++)
#pragma unroll
        for (int nt = 0; nt < 8; nt++)
#pragma unroll
            for (int q = 0; q < 4; q++) acc[mi][nt][q] = 0.f;

    auto compute = [&](int s) {
        const uint32_t uA = sb + (uint32_t)s * STAGE_B;
        const uint32_t uB = uA + A_TILE;
#pragma unroll
        for (int ks = 0; ks < 2; ks++) {
            uint32_t ah[2][4], al[2][4], bb[4][4];
#pragma unroll
            for (int mi = 0; mi < 2; mi++) {
                int row = wm0 + mi * 16 + af_r;
                int c = ks * 2 + af_c;
                ldsm4(ah[mi], uA + row * 128 + (((c    ) ^ (row & 7)) << 4));
                ldsm4(al[mi], uA + row * 128 + (((c + 4) ^ (row & 7)) << 4));
            }
#pragma unroll
            for (int np = 0; np < 4; np++) {
                int row = wn0 + np * 16 + bf_r;
                int c = ks * 2 + bf_c;
                ldsm4(bb[np], uB + row * 128 + ((c ^ (row & 7)) << 4));
            }
#pragma unroll
            for (int mi = 0; mi < 2; mi++)
#pragma unroll
                for (int nt = 0; nt < 8; nt++)
                    mma16816(acc[mi][nt], ah[mi], &bb[nt >> 1][(nt & 1) * 2]);
#pragma unroll
            for (int mi = 0; mi < 2; mi++)
#pragma unroll
                for (int nt = 0; nt < 8; nt++)
                    mma16816(acc[mi][nt], al[mi], &bb[nt >> 1][(nt & 1) * 2]);
#pragma unroll
            for (int np = 0; np < 4; np++) {
                int row = wn0 + np * 16 + bf_r;
                int c = ks * 2 + bf_c + 4;
                ldsm4(bb[np], uB + row * 128 + ((c ^ (row & 7)) << 4));
            }
#pragma unroll
            for (int mi = 0; mi < 2; mi++)
#pragma unroll
                for (int nt = 0; nt < 8; nt++)
                    mma16816(acc[mi][nt], ah[mi], &bb[nt >> 1][(nt & 1) * 2]);
        }
    };

    for (int s = 0; s < NSTAGE - 1; s++) { issue(s, s); CP_COMMIT(); }
    for (int ci = 0; ci < 32; ci++) {
        CP_WAIT1();
        __syncthreads();
        compute(ci % NSTAGE);
        if (ci + NSTAGE - 1 < 32) issue(ci + NSTAGE - 1, (ci + NSTAGE - 1) % NSTAGE);
        CP_COMMIT();
    }

    const int er = lane >> 2, ec = (lane & 3) * 2;
    float bv[8][2];
#pragma unroll
    for (int nt = 0; nt < 8; nt++) {
        bv[nt][0] = __ldg(bias + n0 + wn0 + nt * 8 + ec);
        bv[nt][1] = __ldg(bias + n0 + wn0 + nt * 8 + ec + 1);
    }
#pragma unroll
    for (int mi = 0; mi < 2; mi++) {
        int r0 = m0 + wm0 + mi * 16 + er;
        if (r0 < N_NODES) {
            float* h0 = H + (size_t)r0 * D + n0 + wn0 + ec;
#pragma unroll
            for (int nt = 0; nt < 8; nt++) {
                float2 o = make_float2(acc[mi][nt][0] + bv[nt][0],
                                       acc[mi][nt][1] + bv[nt][1]);
                *(float2*)(h0 + nt * 8) = o;
            }
        }
        int r1 = r0 + 8;
        if (r1 < N_NODES) {
            float* h1 = H + (size_t)r1 * D + n0 + wn0 + ec;
#pragma unroll
            for (int nt = 0; nt < 8; nt++) {
                float2 o = make_float2(acc[mi][nt][2] + bv[nt][0],
                                       acc[mi][nt][3] + bv[nt][1]);
                *(float2*)(h1 + nt * 8) = o;
            }
        }
    }
}

// ---------------- LayerNorm + ReLU + residual (+ fused split, row offset) ---
__global__ void __launch_bounds__(128) ln_kernel(
    const float* __restrict__ H, const float* __restrict__ Xin,
    const float* __restrict__ gg, const float* __restrict__ bb,
    float* __restrict__ Xout,
    __nv_bfloat16* __restrict__ hi, __nv_bfloat16* __restrict__ lo, int row0)
{
    int row = row0 + blockIdx.x;
    int t = threadIdx.x;
    int lane = t & 31, wid = t >> 5;

    float4 v = ((const float4*)(H + (size_t)row * D))[t];
    float s  = v.x + v.y + v.z + v.w;
    float sq = v.x * v.x + v.y * v.y + v.z * v.z + v.w * v.w;

#pragma unroll
    for (int off = 16; off > 0; off >>= 1) {
        s  += __shfl_xor_sync(0xFFFFFFFFu, s,  off);
        sq += __shfl_xor_sync(0xFFFFFFFFu, sq, off);
    }
    __shared__ float ss[4], sqs[4];
    if (lane == 0) { ss[wid] = s; sqs[wid] = sq; }
    __syncthreads();
    s  = ss[0]  + ss[1]  + ss[2]  + ss[3];
    sq = sqs[0] + sqs[1] + sqs[2] + sqs[3];

    float mean = s * (1.0f / D);
    float var  = sq * (1.0f / D) - mean * mean;
    float rr   = rsqrtf(var + LN_EPS);

    float4 g4 = ((const float4*)gg)[t];
    float4 b4 = ((const float4*)bb)[t];
    float4 xi = ((const float4*)(Xin + (size_t)row * D))[t];

    float4 o;
    o.x = fmaxf((v.x - mean) * rr * g4.x + b4.x, 0.f) + xi.x;
    o.y = fmaxf((v.y - mean) * rr * g4.y + b4.y, 0.f) + xi.y;
    o.z = fmaxf((v.z - mean) * rr * g4.z + b4.z, 0.f) + xi.z;
    o.w = fmaxf((v.w - mean) * rr * g4.w + b4.w, 0.f) + xi.w;
    ((float4*)(Xout + (size_t)row * D))[t] = o;

    __nv_bfloat16 h0, h1, h2, h3, l0, l1, l2, l3;
    split2(o.x, h0, l0); split2(o.y, h1, l1);
    split2(o.z, h2, l2); split2(o.w, h3, l3);
    ((uint2*)(hi + (size_t)row * D))[t] = make_uint2(pk(h0, h1), pk(h2, h3));
    ((uint2*)(lo + (size_t)row * D))[t] = make_uint2(pk(l0, l1), pk(l2, l3));
}

// ---------------- launch ----------------------------------------------------
extern "C" void kernel_launch(void* const* d_in, const int* in_sizes, int n_in,
                              void* d_out, int out_size)
{
    const float* x   = (const float*)d_in[0];
    const int*   ei  = (const int*)  d_in[1];
    const float* Wl  = (const float*)d_in[2];
    const float* Wr  = (const float*)d_in[3];
    const float* b   = (const float*)d_in[4];
    const float* lng = (const float*)d_in[5];
    const float* lnb = (const float*)d_in[6];
    float* out = (float*)d_out;

    float *h, *x0, *x1, *inv;
    int *deg, *rp, *cur, *bsum, *adj;
    __nv_bfloat16 *aH, *aL, *xH, *xL, *wlH, *wlL, *wrH, *wrL;
    cudaGetSymbolAddress((void**)&h,    g_h);
    cudaGetSymbolAddress((void**)&x0,   g_x0);
    cudaGetSymbolAddress((void**)&x1,   g_x1);
    cudaGetSymbolAddress((void**)&inv,  g_inv);
    cudaGetSymbolAddress((void**)&deg,  g_deg);
    cudaGetSymbolAddress((void**)&rp,   g_rp);
    cudaGetSymbolAddress((void**)&cur,  g_cur);
    cudaGetSymbolAddress((void**)&bsum, g_bsum);
    cudaGetSymbolAddress((void**)&adj,  g_adj);
    cudaGetSymbolAddress((void**)&aH,   g_aH);
    cudaGetSymbolAddress((void**)&aL,   g_aL);
    cudaGetSymbolAddress((void**)&xH,   g_xH);
    cudaGetSymbolAddress((void**)&xL,   g_xL);
    cudaGetSymbolAddress((void**)&wlH,  g_wlH);
    cudaGetSymbolAddress((void**)&wlL,  g_wlL);
    cudaGetSymbolAddress((void**)&wrH,  g_wrH);
    cudaGetSymbolAddress((void**)&wrL,  g_wrL);

    cudaFuncSetAttribute(gemm_tc_kernel,
                         cudaFuncAttributeMaxDynamicSharedMemorySize, GEMM_SMEM);

    cudaStream_t s2;
    cudaStreamCreateWithFlags(&s2, cudaStreamNonBlocking);
    cudaEvent_t evA[L_LAYERS][N_MCHUNK], evG[L_LAYERS][N_MCHUNK];
    for (int l = 0; l < L_LAYERS; l++)
        for (int c = 0; c < N_MCHUNK; c++) {
            cudaEventCreateWithFlags(&evA[l][c], cudaEventDisableTiming);
            cudaEventCreateWithFlags(&evG[l][c], cudaEventDisableTiming);
        }

    // ---- CSR build + pre-splits (serial on stream 0) ----
    zero_deg_kernel<<<(N_NODES + 255) / 256, 256>>>(deg);
    count_kernel<<<(N_EDGES + 255) / 256, 256>>>(ei, deg);
    scan1_kernel<<<SCAN_NBLK, SCAN_BS>>>(deg, rp, bsum);
    scan2_kernel<<<1, 256>>>(bsum);
    scan3_kernel<<<(N_NODES + 255) / 256, 256>>>(deg, rp, cur, inv, bsum);
    fill_kernel<<<(N_EDGES + 255) / 256, 256>>>(ei, cur, adj);

    split_kernel<<<N_NODES, 128>>>(x, xH, xL);
    split_kernel<<<L_LAYERS * D, 128>>>(Wl, wlH, wlL);
    split_kernel<<<L_LAYERS * D, 128>>>(Wr, wrH, wrL);

    const float* xin = x;
    float* outs[L_LAYERS] = { x0, x1, out };

    for (int l = 0; l < L_LAYERS; l++) {
        int mblk0[N_MCHUNK], nmblk[N_MCHUNK], nd0[N_MCHUNK], nd1[N_MCHUNK];
        for (int c = 0; c < N_MCHUNK; c++) {
            mblk0[c] = c * MBLK_PER_CHUNK;
            int e = mblk0[c] + MBLK_PER_CHUNK;
            if (e > MBLK_TOTAL) e = MBLK_TOTAL;
            nmblk[c] = e - mblk0[c];
            nd0[c] = mblk0[c] * 128;
            nd1[c] = e * 128; if (nd1[c] > N_NODES) nd1[c] = N_NODES;
        }

        for (int c = 0; c < N_MCHUNK; c++) {
            int nnodes = nd1[c] - nd0[c];
            agg_kernel<<<(nnodes + 7) / 8, 256>>>(xin, rp, deg, inv, adj,
                                                  aH, aL, nd0[c], nd1[c]);
            cudaEventRecord(evA[l][c], 0);
        }
        for (int c = 0; c < N_MCHUNK; c++) {
            cudaStreamWaitEvent(s2, evA[l][c], 0);
            dim3 g(D / 128, nmblk[c]);
            gemm_tc_kernel<<<g, 256, GEMM_SMEM, s2>>>(
                aH, aL, xH, xL,
                wlH + (size_t)l * D * D, wlL + (size_t)l * D * D,
                wrH + (size_t)l * D * D, wrL + (size_t)l * D * D,
                b + (size_t)l * D, h, mblk0[c]);
            cudaEventRecord(evG[l][c], s2);
        }
        for (int c = 0; c < N_MCHUNK; c++) {
            cudaStreamWaitEvent(0, evG[l][c], 0);
            int nnodes = nd1[c] - nd0[c];
            ln_kernel<<<nnodes, 128>>>(h, xin, lng + (size_t)l * D,
                                       lnb + (size_t)l * D, outs[l],
                                       xH, xL, nd0[c]);
        }
        xin = outs[l];
    }

    for (int l = 0; l < L_LAYERS; l++)
        for (int c = 0; c < N_MCHUNK; c++) {
            cudaEventDestroy(evA[l][c]);
            cudaEventDestroy(evG[l][c]);
        }
    cudaStreamDestroy(s2);
}

// round 12
// speedup vs baseline: 1.3815x; 1.2011x over previous
#include <cuda_runtime.h>
#include <cuda_fp16.h>
#include <cstdint>
#include <math.h>

#define N_NODES 100000
#define N_EDGES 819200
#define D 512
#define L_LAYERS 3
#define LN_EPS 1e-5f
#define SCAN_BS 512
#define SCAN_NBLK ((N_NODES + SCAN_BS - 1) / SCAN_BS)   // 196

#define N_MCHUNK 4
#define MBLK_TOTAL ((N_NODES + 127) / 128)              // 782
#define MBLK_PER_CHUNK ((MBLK_TOTAL + N_MCHUNK - 1) / N_MCHUNK)  // 196

// ---------------- scratch (static device globals; no allocation) ------------
__device__ float g_h  [(size_t)N_NODES * D];
__device__ float g_x0 [(size_t)N_NODES * D];
__device__ float g_x1 [(size_t)N_NODES * D];
__device__ float g_inv[N_NODES];
__device__ int   g_deg[N_NODES];
__device__ int   g_rp [N_NODES];
__device__ int   g_cur[N_NODES];
__device__ int   g_bsum[256];
__device__ int   g_adj[N_EDGES];
__device__ __align__(16) __half g_aH[(size_t)N_NODES * D];
__device__ __align__(16) __half g_xH[(size_t)N_NODES * D];
__device__ __align__(16) __half g_wlH[L_LAYERS * D * D];
__device__ __align__(16) __half g_wlL[L_LAYERS * D * D];
__device__ __align__(16) __half g_wrH[L_LAYERS * D * D];
__device__ __align__(16) __half g_wrL[L_LAYERS * D * D];

// ---------------- helpers ---------------------------------------------------
__device__ __forceinline__ uint32_t smem_u32(const void* p) {
    uint32_t a;
    asm("{ .reg .u64 t; cvta.to.shared.u64 t, %1; cvt.u32.u64 %0, t; }"
        : "=r"(a) : "l"(p));
    return a;
}
__device__ __forceinline__ uint32_t h2u(__half2 h) {
    return *(uint32_t*)&h;
}
__device__ __forceinline__ void ldsm4(uint32_t* r, uint32_t addr) {
    asm volatile("ldmatrix.sync.aligned.m8n8.x4.shared.b16 {%0,%1,%2,%3}, [%4];"
                 : "=r"(r[0]), "=r"(r[1]), "=r"(r[2]), "=r"(r[3]) : "r"(addr));
}
__device__ __forceinline__ void mma16816(float* c, const uint32_t* a, const uint32_t* b) {
    asm volatile("mma.sync.aligned.m16n8k16.row.col.f32.f16.f16.f32 "
                 "{%0,%1,%2,%3}, {%4,%5,%6,%7}, {%8,%9}, {%0,%1,%2,%3};"
                 : "+f"(c[0]), "+f"(c[1]), "+f"(c[2]), "+f"(c[3])
                 : "r"(a[0]), "r"(a[1]), "r"(a[2]), "r"(a[3]), "r"(b[0]), "r"(b[1]));
}
__device__ __forceinline__ void cp16(uint32_t dst, const void* src, uint32_t bytes) {
    asm volatile("cp.async.cg.shared.global [%0], [%1], 16, %2;"
                 :: "r"(dst), "l"(src), "r"(bytes) : "memory");
}
#define CP_COMMIT() asm volatile("cp.async.commit_group;" ::: "memory")
#define CP_WAITG(n) asm volatile("cp.async.wait_group %0;" :: "n"(n) : "memory")

// ---------------- CSR build -------------------------------------------------
__global__ void zero_deg_kernel(int* __restrict__ deg) {
    int i = blockIdx.x * blockDim.x + threadIdx.x;
    if (i < N_NODES) deg[i] = 0;
}
__global__ void count_kernel(const int* __restrict__ ei, int* __restrict__ deg) {
    int e = blockIdx.x * blockDim.x + threadIdx.x;
    if (e < N_EDGES) atomicAdd(&deg[ei[N_EDGES + e]], 1);
}
__global__ void __launch_bounds__(SCAN_BS) scan1_kernel(
    const int* __restrict__ deg, int* __restrict__ rp, int* __restrict__ bsum)
{
    __shared__ int sh[SCAN_BS];
    int t = threadIdx.x;
    int i = blockIdx.x * SCAN_BS + t;
    int v = (i < N_NODES) ? deg[i] : 0;
    sh[t] = v; __syncthreads();
    for (int off = 1; off < SCAN_BS; off <<= 1) {
        int u = (t >= off) ? sh[t - off] : 0;
        __syncthreads();
        sh[t] += u;
        __syncthreads();
    }
    if (i < N_NODES) rp[i] = sh[t] - v;
    if (t == SCAN_BS - 1) bsum[blockIdx.x] = sh[t];
}
__global__ void __launch_bounds__(256) scan2_kernel(int* __restrict__ bsum) {
    __shared__ int sh[256];
    int t = threadIdx.x;
    int v = (t < SCAN_NBLK) ? bsum[t] : 0;
    sh[t] = v; __syncthreads();
    for (int off = 1; off < 256; off <<= 1) {
        int u = (t >= off) ? sh[t - off] : 0;
        __syncthreads();
        sh[t] += u;
        __syncthreads();
    }
    if (t < SCAN_NBLK) bsum[t] = sh[t] - v;
}
__global__ void scan3_kernel(const int* __restrict__ deg, int* __restrict__ rp,
                             int* __restrict__ cur, float* __restrict__ inv,
                             const int* __restrict__ bsum)
{
    int i = blockIdx.x * blockDim.x + threadIdx.x;
    if (i < N_NODES) {
        int r = rp[i] + bsum[i >> 9];
        rp[i] = r;
        cur[i] = r;
        inv[i] = 1.0f / (float)max(deg[i], 1);
    }
}
__global__ void fill_kernel(const int* __restrict__ ei, int* __restrict__ cur,
                            int* __restrict__ adj)
{
    int e = blockIdx.x * blockDim.x + threadIdx.x;
    if (e < N_EDGES) {
        int slot = atomicAdd(&cur[ei[N_EDGES + e]], 1);
        adj[slot] = ei[e];
    }
}

// ---------------- CSR gather aggregation + mean -> fp16 (node range) --------
__global__ void __launch_bounds__(256) agg_kernel(
    const float* __restrict__ x, const int* __restrict__ rp,
    const int* __restrict__ deg, const float* __restrict__ inv,
    const int* __restrict__ adj,
    __half* __restrict__ hi, int node0, int node1)
{
    int node = node0 + blockIdx.x * 8 + (threadIdx.x >> 5);
    if (node >= node1) return;
    int lane = threadIdx.x & 31;

    float4 acc[4];
#pragma unroll
    for (int q = 0; q < 4; q++) acc[q] = make_float4(0.f, 0.f, 0.f, 0.f);

    int beg = __ldg(&rp[node]);
    int d   = __ldg(&deg[node]);
    int j = 0;
    for (; j + 2 <= d; j += 2) {
        int s0 = __ldg(&adj[beg + j]);
        int s1 = __ldg(&adj[beg + j + 1]);
        const float4* r0 = (const float4*)(x + (size_t)s0 * D);
        const float4* r1 = (const float4*)(x + (size_t)s1 * D);
        float4 v0[4], v1[4];
#pragma unroll
        for (int q = 0; q < 4; q++) v0[q] = __ldg(r0 + lane + q * 32);
#pragma unroll
        for (int q = 0; q < 4; q++) v1[q] = __ldg(r1 + lane + q * 32);
#pragma unroll
        for (int q = 0; q < 4; q++) {
            acc[q].x += v0[q].x + v1[q].x;
            acc[q].y += v0[q].y + v1[q].y;
            acc[q].z += v0[q].z + v1[q].z;
            acc[q].w += v0[q].w + v1[q].w;
        }
    }
    if (j < d) {
        int s0 = __ldg(&adj[beg + j]);
        const float4* r0 = (const float4*)(x + (size_t)s0 * D);
#pragma unroll
        for (int q = 0; q < 4; q++) {
            float4 v = __ldg(r0 + lane + q * 32);
            acc[q].x += v.x; acc[q].y += v.y; acc[q].z += v.z; acc[q].w += v.w;
        }
    }
    float s = __ldg(&inv[node]);
    uint2* ph = (uint2*)(hi + (size_t)node * D);
#pragma unroll
    for (int q = 0; q < 4; q++) {
        float4 v = acc[q];
        __half2 p0 = __floats2half2_rn(v.x * s, v.y * s);
        __half2 p1 = __floats2half2_rn(v.z * s, v.w * s);
        ph[lane + q * 32] = make_uint2(h2u(p0), h2u(p1));
    }
}

// ---------------- fp32 -> fp16 (hi only) ------------------------------------
__global__ void __launch_bounds__(128) splitx_kernel(
    const float* __restrict__ in, __half* __restrict__ hi)
{
    size_t row = blockIdx.x;
    int t = threadIdx.x;
    float4 v = ((const float4*)(in + row * D))[t];
    __half2 p0 = __floats2half2_rn(v.x, v.y);
    __half2 p1 = __floats2half2_rn(v.z, v.w);
    ((uint2*)(hi + row * D))[t] = make_uint2(h2u(p0), h2u(p1));
}

// ---------------- fp32 -> (fp16 hi, fp16 lo) for weights --------------------
__global__ void __launch_bounds__(128) splitw_kernel(
    const float* __restrict__ in,
    __half* __restrict__ hi, __half* __restrict__ lo)
{
    size_t row = blockIdx.x;
    int t = threadIdx.x;
    float4 v = ((const float4*)(in + row * D))[t];
    __half h0 = __float2half_rn(v.x);
    __half h1 = __float2half_rn(v.y);
    __half h2 = __float2half_rn(v.z);
    __half h3 = __float2half_rn(v.w);
    __half l0 = __float2half_rn(v.x - __half2float(h0));
    __half l1 = __float2half_rn(v.y - __half2float(h1));
    __half l2 = __float2half_rn(v.z - __half2float(h2));
    __half l3 = __float2half_rn(v.w - __half2float(h3));
    ((uint2*)(hi + row * D))[t] =
        make_uint2(h2u(__halves2half2(h0, h1)), h2u(__halves2half2(h2, h3)));
    ((uint2*)(lo + row * D))[t] =
        make_uint2(h2u(__halves2half2(l0, l1)), h2u(__halves2half2(l2, l3)));
}

// ---------------- fp16 2-term tensor-core GEMM (K=1024 fused, M-chunked) ----
// H = agg@Wl^T + x@Wr^T + bias.  A rounded to fp16; W split (hi,lo).
// Per k-step: A*Wh + A*Wl.  k64 chunks; stage = Ah(16K)+Bh(16K)+Bl(16K)=48KB;
// 2-stage double buffer = 96KB -> 2 CTAs/SM.
#define NSTAGE 2
#define TILE_B 16384
#define STAGE_B (3 * TILE_B)
#define GEMM_SMEM (NSTAGE * STAGE_B)
#define N_CHUNK 16

__global__ void __launch_bounds__(256, 2) gemm_tc_kernel(
    const __half* __restrict__ aH, const __half* __restrict__ xH,
    const __half* __restrict__ wlH, const __half* __restrict__ wlL,
    const __half* __restrict__ wrH, const __half* __restrict__ wrL,
    const float* __restrict__ bias, float* __restrict__ H, int mblk0)
{
    extern __shared__ __align__(1024) char smem[];
    const uint32_t sb = smem_u32(smem);
    const int tid = threadIdx.x, lane = tid & 31, wid = tid >> 5;
    const int m0 = (mblk0 + blockIdx.y) * 128, n0 = blockIdx.x * 128;

    const int lr = tid >> 1;                 // row 0..127
    const int lc = (tid & 1) * 4;            // chunk base 0 or 4
    const int arow = m0 + lr;
    const uint32_t abytes = (arow < N_NODES) ? 16u : 0u;
    const size_t aoff = (size_t)(arow < N_NODES ? arow : 0) * D;
    const size_t woff = (size_t)(n0 + lr) * D;
    const uint32_t rb = (uint32_t)lr * 128;
    const uint32_t r7 = (uint32_t)(lr & 7);

    auto issue = [&](int ci, int s) {
        const int ph = ci >> 3;
        const int k0 = (ci & 7) * 64;
        const __half* pA  = (ph ? xH : aH) + aoff + k0;
        const __half* pBH = (ph ? wrH : wlH) + woff + k0;
        const __half* pBL = (ph ? wrL : wlL) + woff + k0;
        const uint32_t uA  = sb + (uint32_t)s * STAGE_B;
        const uint32_t uBH = uA + TILE_B;
        const uint32_t uBL = uBH + TILE_B;
#pragma unroll
        for (int j = 0; j < 4; j++) {
            const uint32_t c = (uint32_t)(lc + j);
            const uint32_t off = rb + ((c ^ r7) << 4);
            cp16(uA  + off, pA  + c * 8, abytes);
            cp16(uBH + off, pBH + c * 8, 16u);
            cp16(uBL + off, pBL + c * 8, 16u);
        }
    };

    const int wm0 = (wid & 3) * 32, wn0 = (wid >> 2) * 64;
    const int af_r = lane & 15;
    const int af_c = lane >> 4;
    const int bf_r = (lane & 7) + ((lane >> 4) & 1) * 8;
    const int bf_c = (lane >> 3) & 1;

    float acc[2][8][4];
#pragma unroll
    for (int mi = 0; mi < 2; mi++)
#pragma unroll
        for (int nt = 0; nt < 8; nt++)
#pragma unroll
            for (int q = 0; q < 4; q++) acc[mi][nt][q] = 0.f;

    auto compute = [&](int s) {
        const uint32_t uA  = sb + (uint32_t)s * STAGE_B;
        const uint32_t uBH = uA + TILE_B;
        const uint32_t uBL = uBH + TILE_B;
#pragma unroll
        for (int ks = 0; ks < 4; ks++) {
            uint32_t ah[2][4], bb[4][4];
#pragma unroll
            for (int mi = 0; mi < 2; mi++) {
                int row = wm0 + mi * 16 + af_r;
                int c = ks * 2 + af_c;
                ldsm4(ah[mi], uA + row * 128 + ((c ^ (row & 7)) << 4));
            }
#pragma unroll
            for (int np = 0; np < 4; np++) {
                int row = wn0 + np * 16 + bf_r;
                int c = ks * 2 + bf_c;
                ldsm4(bb[np], uBH + row * 128 + ((c ^ (row & 7)) << 4));
            }
#pragma unroll
            for (int mi = 0; mi < 2; mi++)
#pragma unroll
                for (int nt = 0; nt < 8; nt++)
                    mma16816(acc[mi][nt], ah[mi], &bb[nt >> 1][(nt & 1) * 2]);
#pragma unroll
            for (int np = 0; np < 4; np++) {
                int row = wn0 + np * 16 + bf_r;
                int c = ks * 2 + bf_c;
                ldsm4(bb[np], uBL + row * 128 + ((c ^ (row & 7)) << 4));
            }
#pragma unroll
            for (int mi = 0; mi < 2; mi++)
#pragma unroll
                for (int nt = 0; nt < 8; nt++)
                    mma16816(acc[mi][nt], ah[mi], &bb[nt >> 1][(nt & 1) * 2]);
        }
    };

    issue(0, 0); CP_COMMIT();
    for (int ci = 0; ci < N_CHUNK; ci++) {
        if (ci + 1 < N_CHUNK) { issue(ci + 1, (ci + 1) & 1); CP_COMMIT(); CP_WAITG(1); }
        else                  { CP_WAITG(0); }
        __syncthreads();
        compute(ci & 1);
        __syncthreads();
    }

    const int er = lane >> 2, ec = (lane & 3) * 2;
    float bv[8][2];
#pragma unroll
    for (int nt = 0; nt < 8; nt++) {
        bv[nt][0] = __ldg(bias + n0 + wn0 + nt * 8 + ec);
        bv[nt][1] = __ldg(bias + n0 + wn0 + nt * 8 + ec + 1);
    }
#pragma unroll
    for (int mi = 0; mi < 2; mi++) {
        int r0 = m0 + wm0 + mi * 16 + er;
        if (r0 < N_NODES) {
            float* h0 = H + (size_t)r0 * D + n0 + wn0 + ec;
#pragma unroll
            for (int nt = 0; nt < 8; nt++) {
                float2 o = make_float2(acc[mi][nt][0] + bv[nt][0],
                                       acc[mi][nt][1] + bv[nt][1]);
                *(float2*)(h0 + nt * 8) = o;
            }
        }
        int r1 = r0 + 8;
        if (r1 < N_NODES) {
            float* h1 = H + (size_t)r1 * D + n0 + wn0 + ec;
#pragma unroll
            for (int nt = 0; nt < 8; nt++) {
                float2 o = make_float2(acc[mi][nt][2] + bv[nt][0],
                                       acc[mi][nt][3] + bv[nt][1]);
                *(float2*)(h1 + nt * 8) = o;
            }
        }
    }
}

// ---------------- LayerNorm + ReLU + residual (+ fp16 hi, row offset) -------
__global__ void __launch_bounds__(128) ln_kernel(
    const float* __restrict__ H, const float* __restrict__ Xin,
    const float* __restrict__ gg, const float* __restrict__ bb,
    float* __restrict__ Xout, __half* __restrict__ hi, int row0)
{
    int row = row0 + blockIdx.x;
    int t = threadIdx.x;
    int lane = t & 31, wid = t >> 5;

    float4 v = ((const float4*)(H + (size_t)row * D))[t];
    float s  = v.x + v.y + v.z + v.w;
    float sq = v.x * v.x + v.y * v.y + v.z * v.z + v.w * v.w;

#pragma unroll
    for (int off = 16; off > 0; off >>= 1) {
        s  += __shfl_xor_sync(0xFFFFFFFFu, s,  off);
        sq += __shfl_xor_sync(0xFFFFFFFFu, sq, off);
    }
    __shared__ float ss[4], sqs[4];
    if (lane == 0) { ss[wid] = s; sqs[wid] = sq; }
    __syncthreads();
    s  = ss[0]  + ss[1]  + ss[2]  + ss[3];
    sq = sqs[0] + sqs[1] + sqs[2] + sqs[3];

    float mean = s * (1.0f / D);
    float var  = sq * (1.0f / D) - mean * mean;
    float rr   = rsqrtf(var + LN_EPS);

    float4 g4 = ((const float4*)gg)[t];
    float4 b4 = ((const float4*)bb)[t];
    float4 xi = ((const float4*)(Xin + (size_t)row * D))[t];

    float4 o;
    o.x = fmaxf((v.x - mean) * rr * g4.x + b4.x, 0.f) + xi.x;
    o.y = fmaxf((v.y - mean) * rr * g4.y + b4.y, 0.f) + xi.y;
    o.z = fmaxf((v.z - mean) * rr * g4.z + b4.z, 0.f) + xi.z;
    o.w = fmaxf((v.w - mean) * rr * g4.w + b4.w, 0.f) + xi.w;
    ((float4*)(Xout + (size_t)row * D))[t] = o;

    __half2 p0 = __floats2half2_rn(o.x, o.y);
    __half2 p1 = __floats2half2_rn(o.z, o.w);
    ((uint2*)(hi + (size_t)row * D))[t] = make_uint2(h2u(p0), h2u(p1));
}

// ---------------- launch ----------------------------------------------------
extern "C" void kernel_launch(void* const* d_in, const int* in_sizes, int n_in,
                              void* d_out, int out_size)
{
    const float* x   = (const float*)d_in[0];
    const int*   ei  = (const int*)  d_in[1];
    const float* Wl  = (const float*)d_in[2];
    const float* Wr  = (const float*)d_in[3];
    const float* b   = (const float*)d_in[4];
    const float* lng = (const float*)d_in[5];
    const float* lnb = (const float*)d_in[6];
    float* out = (float*)d_out;

    float *h, *x0, *x1, *inv;
    int *deg, *rp, *cur, *bsum, *adj;
    __half *aH, *xH, *wlH, *wlL, *wrH, *wrL;
    cudaGetSymbolAddress((void**)&h,    g_h);
    cudaGetSymbolAddress((void**)&x0,   g_x0);
    cudaGetSymbolAddress((void**)&x1,   g_x1);
    cudaGetSymbolAddress((void**)&inv,  g_inv);
    cudaGetSymbolAddress((void**)&deg,  g_deg);
    cudaGetSymbolAddress((void**)&rp,   g_rp);
    cudaGetSymbolAddress((void**)&cur,  g_cur);
    cudaGetSymbolAddress((void**)&bsum, g_bsum);
    cudaGetSymbolAddress((void**)&adj,  g_adj);
    cudaGetSymbolAddress((void**)&aH,   g_aH);
    cudaGetSymbolAddress((void**)&xH,   g_xH);
    cudaGetSymbolAddress((void**)&wlH,  g_wlH);
    cudaGetSymbolAddress((void**)&wlL,  g_wlL);
    cudaGetSymbolAddress((void**)&wrH,  g_wrH);
    cudaGetSymbolAddress((void**)&wrL,  g_wrL);

    cudaFuncSetAttribute(gemm_tc_kernel,
                         cudaFuncAttributeMaxDynamicSharedMemorySize, GEMM_SMEM);

    cudaStream_t s2;
    cudaStreamCreateWithFlags(&s2, cudaStreamNonBlocking);
    cudaEvent_t evA[L_LAYERS][N_MCHUNK], evG[L_LAYERS][N_MCHUNK];
    for (int l = 0; l < L_LAYERS; l++)
        for (int c = 0; c < N_MCHUNK; c++) {
            cudaEventCreateWithFlags(&evA[l][c], cudaEventDisableTiming);
            cudaEventCreateWithFlags(&evG[l][c], cudaEventDisableTiming);
        }

    // ---- CSR build + pre-splits (serial on stream 0) ----
    zero_deg_kernel<<<(N_NODES + 255) / 256, 256>>>(deg);
    count_kernel<<<(N_EDGES + 255) / 256, 256>>>(ei, deg);
    scan1_kernel<<<SCAN_NBLK, SCAN_BS>>>(deg, rp, bsum);
    scan2_kernel<<<1, 256>>>(bsum);
    scan3_kernel<<<(N_NODES + 255) / 256, 256>>>(deg, rp, cur, inv, bsum);
    fill_kernel<<<(N_EDGES + 255) / 256, 256>>>(ei, cur, adj);

    splitx_kernel<<<N_NODES, 128>>>(x, xH);
    splitw_kernel<<<L_LAYERS * D, 128>>>(Wl, wlH, wlL);
    splitw_kernel<<<L_LAYERS * D, 128>>>(Wr, wrH, wrL);

    const float* xin = x;
    float* outs[L_LAYERS] = { x0, x1, out };

    for (int l = 0; l < L_LAYERS; l++) {
        int mblk0[N_MCHUNK], nmblk[N_MCHUNK], nd0[N_MCHUNK], nd1[N_MCHUNK];
        for (int c = 0; c < N_MCHUNK; c++) {
            mblk0[c] = c * MBLK_PER_CHUNK;
            int e = mblk0[c] + MBLK_PER_CHUNK;
            if (e > MBLK_TOTAL) e = MBLK_TOTAL;
            nmblk[c] = e - mblk0[c];
            nd0[c] = mblk0[c] * 128;
            nd1[c] = e * 128; if (nd1[c] > N_NODES) nd1[c] = N_NODES;
        }

        for (int c = 0; c < N_MCHUNK; c++) {
            int nnodes = nd1[c] - nd0[c];
            agg_kernel<<<(nnodes + 7) / 8, 256>>>(xin, rp, deg, inv, adj,
                                                  aH, nd0[c], nd1[c]);
            cudaEventRecord(evA[l][c], 0);
        }
        for (int c = 0; c < N_MCHUNK; c++) {
            cudaStreamWaitEvent(s2, evA[l][c], 0);
            dim3 g(D / 128, nmblk[c]);
            gemm_tc_kernel<<<g, 256, GEMM_SMEM, s2>>>(
                aH, xH,
                wlH + (size_t)l * D * D, wlL + (size_t)l * D * D,
                wrH + (size_t)l * D * D, wrL + (size_t)l * D * D,
                b + (size_t)l * D, h, mblk0[c]);
            cudaEventRecord(evG[l][c], s2);
        }
        for (int c = 0; c < N_MCHUNK; c++) {
            cudaStreamWaitEvent(0, evG[l][c], 0);
            int nnodes = nd1[c] - nd0[c];
            ln_kernel<<<nnodes, 128>>>(h, xin, lng + (size_t)l * D,
                                       lnb + (size_t)l * D, outs[l],
                                       xH, nd0[c]);
        }
        xin = outs[l];
    }

    for (int l = 0; l < L_LAYERS; l++)
        for (int c = 0; c < N_MCHUNK; c++) {
            cudaEventDestroy(evA[l][c]);
            cudaEventDestroy(evG[l][c]);
        }
    cudaStreamDestroy(s2);
}

// round 14
// speedup vs baseline: 2.1856x; 1.5821x over previous
#include <cuda_runtime.h>
#include <cuda_fp16.h>
#include <cstdint>
#include <math.h>

#define N_NODES 100000
#define N_EDGES 819200
#define D 512
#define L_LAYERS 3
#define LN_EPS 1e-5f
#define SCAN_BS 512
#define SCAN_NBLK ((N_NODES + SCAN_BS - 1) / SCAN_BS)   // 196

#define N_MCHUNK 4
#define MBLK_TOTAL ((N_NODES + 127) / 128)              // 782
#define MBLK_PER_CHUNK ((MBLK_TOTAL + N_MCHUNK - 1) / N_MCHUNK)  // 196

// ---------------- scratch (static device globals; no allocation) ------------
__device__ float g_h  [(size_t)N_NODES * D];
__device__ float g_x0 [(size_t)N_NODES * D];
__device__ float g_x1 [(size_t)N_NODES * D];
__device__ float g_inv[N_NODES];
__device__ int   g_deg[N_NODES];
__device__ int   g_rp [N_NODES];
__device__ int   g_cur[N_NODES];
__device__ int   g_bsum[256];
__device__ int   g_adj[N_EDGES];
__device__ __align__(16) __half g_aH[(size_t)N_NODES * D];
__device__ __align__(16) __half g_xH[(size_t)N_NODES * D];
__device__ __align__(16) __half g_wl[L_LAYERS * D * D];
__device__ __align__(16) __half g_wr[L_LAYERS * D * D];

// ---------------- helpers ---------------------------------------------------
__device__ __forceinline__ uint32_t smem_u32(const void* p) {
    uint32_t a;
    asm("{ .reg .u64 t; cvta.to.shared.u64 t, %1; cvt.u32.u64 %0, t; }"
        : "=r"(a) : "l"(p));
    return a;
}
__device__ __forceinline__ uint32_t h2u(__half2 h) {
    return *(uint32_t*)&h;
}
__device__ __forceinline__ void ldsm4(uint32_t* r, uint32_t addr) {
    asm volatile("ldmatrix.sync.aligned.m8n8.x4.shared.b16 {%0,%1,%2,%3}, [%4];"
                 : "=r"(r[0]), "=r"(r[1]), "=r"(r[2]), "=r"(r[3]) : "r"(addr));
}
__device__ __forceinline__ void mma16816(float* c, const uint32_t* a, const uint32_t* b) {
    asm volatile("mma.sync.aligned.m16n8k16.row.col.f32.f16.f16.f32 "
                 "{%0,%1,%2,%3}, {%4,%5,%6,%7}, {%8,%9}, {%0,%1,%2,%3};"
                 : "+f"(c[0]), "+f"(c[1]), "+f"(c[2]), "+f"(c[3])
                 : "r"(a[0]), "r"(a[1]), "r"(a[2]), "r"(a[3]), "r"(b[0]), "r"(b[1]));
}
__device__ __forceinline__ void cp16(uint32_t dst, const void* src, uint32_t bytes) {
    asm volatile("cp.async.cg.shared.global [%0], [%1], 16, %2;"
                 :: "r"(dst), "l"(src), "r"(bytes) : "memory");
}
#define CP_COMMIT() asm volatile("cp.async.commit_group;" ::: "memory")
#define CP_WAIT1()  asm volatile("cp.async.wait_group 1;" ::: "memory")
#define CP_WAIT0()  asm volatile("cp.async.wait_group 0;" ::: "memory")

// ---------------- CSR build -------------------------------------------------
__global__ void zero_deg_kernel(int* __restrict__ deg) {
    int i = blockIdx.x * blockDim.x + threadIdx.x;
    if (i < N_NODES) deg[i] = 0;
}
__global__ void count_kernel(const int* __restrict__ ei, int* __restrict__ deg) {
    int e = blockIdx.x * blockDim.x + threadIdx.x;
    if (e < N_EDGES) atomicAdd(&deg[ei[N_EDGES + e]], 1);
}
__global__ void __launch_bounds__(SCAN_BS) scan1_kernel(
    const int* __restrict__ deg, int* __restrict__ rp, int* __restrict__ bsum)
{
    __shared__ int sh[SCAN_BS];
    int t = threadIdx.x;
    int i = blockIdx.x * SCAN_BS + t;
    int v = (i < N_NODES) ? deg[i] : 0;
    sh[t] = v; __syncthreads();
    for (int off = 1; off < SCAN_BS; off <<= 1) {
        int u = (t >= off) ? sh[t - off] : 0;
        __syncthreads();
        sh[t] += u;
        __syncthreads();
    }
    if (i < N_NODES) rp[i] = sh[t] - v;
    if (t == SCAN_BS - 1) bsum[blockIdx.x] = sh[t];
}
__global__ void __launch_bounds__(256) scan2_kernel(int* __restrict__ bsum) {
    __shared__ int sh[256];
    int t = threadIdx.x;
    int v = (t < SCAN_NBLK) ? bsum[t] : 0;
    sh[t] = v; __syncthreads();
    for (int off = 1; off < 256; off <<= 1) {
        int u = (t >= off) ? sh[t - off] : 0;
        __syncthreads();
        sh[t] += u;
        __syncthreads();
    }
    if (t < SCAN_NBLK) bsum[t] = sh[t] - v;
}
__global__ void scan3_kernel(const int* __restrict__ deg, int* __restrict__ rp,
                             int* __restrict__ cur, float* __restrict__ inv,
                             const int* __restrict__ bsum)
{
    int i = blockIdx.x * blockDim.x + threadIdx.x;
    if (i < N_NODES) {
        int r = rp[i] + bsum[i >> 9];
        rp[i] = r;
        cur[i] = r;
        inv[i] = 1.0f / (float)max(deg[i], 1);
    }
}
__global__ void fill_kernel(const int* __restrict__ ei, int* __restrict__ cur,
                            int* __restrict__ adj)
{
    int e = blockIdx.x * blockDim.x + threadIdx.x;
    if (e < N_EDGES) {
        int slot = atomicAdd(&cur[ei[N_EDGES + e]], 1);
        adj[slot] = ei[e];
    }
}

// ---------------- CSR gather aggregation (fp16 gather) + mean -> fp16 -------
// one warp per node; lane owns 2 uint4 (16 halves) of the 512-wide fp16 row
__global__ void __launch_bounds__(256) agg_kernel(
    const __half* __restrict__ xh, const int* __restrict__ rp,
    const int* __restrict__ deg, const float* __restrict__ inv,
    const int* __restrict__ adj,
    __half* __restrict__ hi, int node0, int node1)
{
    int node = node0 + blockIdx.x * 8 + (threadIdx.x >> 5);
    if (node >= node1) return;
    int lane = threadIdx.x & 31;

    float acc[16];
#pragma unroll
    for (int q = 0; q < 16; q++) acc[q] = 0.f;

    int beg = __ldg(&rp[node]);
    int d   = __ldg(&deg[node]);
    int j = 0;
    for (; j + 2 <= d; j += 2) {
        int s0 = __ldg(&adj[beg + j]);
        int s1 = __ldg(&adj[beg + j + 1]);
        const uint4* r0 = (const uint4*)(xh + (size_t)s0 * D);
        const uint4* r1 = (const uint4*)(xh + (size_t)s1 * D);
        uint4 a0 = __ldg(r0 + lane), a1 = __ldg(r0 + lane + 32);
        uint4 b0 = __ldg(r1 + lane), b1 = __ldg(r1 + lane + 32);
        const uint32_t* pa = &a0.x;
        const uint32_t* pb = &b0.x;
#pragma unroll
        for (int q = 0; q < 4; q++) {
            float2 fa = __half22float2(*(const __half2*)&pa[q]);
            float2 fb = __half22float2(*(const __half2*)&pb[q]);
            acc[2 * q]     += fa.x + fb.x;
            acc[2 * q + 1] += fa.y + fb.y;
        }
        const uint32_t* pa2 = &a1.x;
        const uint32_t* pb2 = &b1.x;
#pragma unroll
        for (int q = 0; q < 4; q++) {
            float2 fa = __half22float2(*(const __half2*)&pa2[q]);
            float2 fb = __half22float2(*(const __half2*)&pb2[q]);
            acc[8 + 2 * q]     += fa.x + fb.x;
            acc[8 + 2 * q + 1] += fa.y + fb.y;
        }
    }
    if (j < d) {
        int s0 = __ldg(&adj[beg + j]);
        const uint4* r0 = (const uint4*)(xh + (size_t)s0 * D);
        uint4 a0 = __ldg(r0 + lane), a1 = __ldg(r0 + lane + 32);
        const uint32_t* pa = &a0.x;
#pragma unroll
        for (int q = 0; q < 4; q++) {
            float2 fa = __half22float2(*(const __half2*)&pa[q]);
            acc[2 * q]     += fa.x;
            acc[2 * q + 1] += fa.y;
        }
        const uint32_t* pa2 = &a1.x;
#pragma unroll
        for (int q = 0; q < 4; q++) {
            float2 fa = __half22float2(*(const __half2*)&pa2[q]);
            acc[8 + 2 * q]     += fa.x;
            acc[8 + 2 * q + 1] += fa.y;
        }
    }
    float s = __ldg(&inv[node]);
    uint4* ph = (uint4*)(hi + (size_t)node * D);
    uint4 o0, o1;
    uint32_t* po0 = &o0.x;
    uint32_t* po1 = &o1.x;
#pragma unroll
    for (int q = 0; q < 4; q++) {
        po0[q] = h2u(__floats2half2_rn(acc[2 * q] * s, acc[2 * q + 1] * s));
        po1[q] = h2u(__floats2half2_rn(acc[8 + 2 * q] * s, acc[8 + 2 * q + 1] * s));
    }
    ph[lane]      = o0;
    ph[lane + 32] = o1;
}

// ---------------- fp32 -> fp16 ----------------------------------------------
__global__ void __launch_bounds__(128) tohalf_kernel(
    const float* __restrict__ in, __half* __restrict__ hi)
{
    size_t row = blockIdx.x;
    int t = threadIdx.x;
    float4 v = ((const float4*)(in + row * D))[t];
    __half2 p0 = __floats2half2_rn(v.x, v.y);
    __half2 p1 = __floats2half2_rn(v.z, v.w);
    ((uint2*)(hi + row * D))[t] = make_uint2(h2u(p0), h2u(p1));
}

// ---------------- fp16 tensor-core GEMM (K=1024 fused, M-chunked) -----------
// H = agg@Wl^T + x@Wr^T + bias, all operands fp16, fp32 accum.
// k64 chunks; stage = A(16K)+W(16K)=32KB; 3-stage = 96KB -> 2 CTAs/SM.
#define NSTAGE 3
#define TILE_B 16384
#define STAGE_B (2 * TILE_B)
#define GEMM_SMEM (NSTAGE * STAGE_B)
#define N_CHUNK 16

__global__ void __launch_bounds__(256, 2) gemm_tc_kernel(
    const __half* __restrict__ aH, const __half* __restrict__ xH,
    const __half* __restrict__ wl, const __half* __restrict__ wr,
    const float* __restrict__ bias, float* __restrict__ H, int mblk0)
{
    extern __shared__ __align__(1024) char smem[];
    const uint32_t sb = smem_u32(smem);
    const int tid = threadIdx.x, lane = tid & 31, wid = tid >> 5;
    const int m0 = (mblk0 + blockIdx.y) * 128, n0 = blockIdx.x * 128;

    const int lr = tid >> 1;                 // row 0..127
    const int lc = (tid & 1) * 4;            // chunk base 0 or 4
    const int arow = m0 + lr;
    const uint32_t abytes = (arow < N_NODES) ? 16u : 0u;
    const size_t aoff = (size_t)(arow < N_NODES ? arow : 0) * D;
    const size_t woff = (size_t)(n0 + lr) * D;
    const uint32_t rb = (uint32_t)lr * 128;
    const uint32_t r7 = (uint32_t)(lr & 7);

    auto issue = [&](int ci, int s) {
        const int ph = ci >> 3;
        const int k0 = (ci & 7) * 64;
        const __half* pA = (ph ? xH : aH) + aoff + k0;
        const __half* pW = (ph ? wr : wl) + woff + k0;
        const uint32_t uA = sb + (uint32_t)s * STAGE_B;
        const uint32_t uW = uA + TILE_B;
#pragma unroll
        for (int j = 0; j < 4; j++) {
            const uint32_t c = (uint32_t)(lc + j);
            const uint32_t off = rb + ((c ^ r7) << 4);
            cp16(uA + off, pA + c * 8, abytes);
            cp16(uW + off, pW + c * 8, 16u);
        }
    };

    const int wm0 = (wid & 3) * 32, wn0 = (wid >> 2) * 64;
    const int af_r = lane & 15;
    const int af_c = lane >> 4;
    const int bf_r = (lane & 7) + ((lane >> 4) & 1) * 8;
    const int bf_c = (lane >> 3) & 1;

    float acc[2][8][4];
#pragma unroll
    for (int mi = 0; mi < 2; mi++)
#pragma unroll
        for (int nt = 0; nt < 8; nt++)
#pragma unroll
            for (int q = 0; q < 4; q++) acc[mi][nt][q] = 0.f;

    auto compute = [&](int s) {
        const uint32_t uA = sb + (uint32_t)s * STAGE_B;
        const uint32_t uW = uA + TILE_B;
#pragma unroll
        for (int ks = 0; ks < 4; ks++) {
            uint32_t ah[2][4], bb[4][4];
#pragma unroll
            for (int mi = 0; mi < 2; mi++) {
                int row = wm0 + mi * 16 + af_r;
                int c = ks * 2 + af_c;
                ldsm4(ah[mi], uA + row * 128 + ((c ^ (row & 7)) << 4));
            }
#pragma unroll
            for (int np = 0; np < 4; np++) {
                int row = wn0 + np * 16 + bf_r;
                int c = ks * 2 + bf_c;
                ldsm4(bb[np], uW + row * 128 + ((c ^ (row & 7)) << 4));
            }
#pragma unroll
            for (int mi = 0; mi < 2; mi++)
#pragma unroll
                for (int nt = 0; nt < 8; nt++)
                    mma16816(acc[mi][nt], ah[mi], &bb[nt >> 1][(nt & 1) * 2]);
        }
    };

    issue(0, 0); CP_COMMIT();
    issue(1, 1); CP_COMMIT();
    for (int ci = 0; ci < N_CHUNK; ci++) {
        if (ci + 1 < N_CHUNK) { CP_WAIT1(); }
        else                  { CP_WAIT0(); }
        __syncthreads();
        compute(ci % NSTAGE);
        if (ci + 2 < N_CHUNK) { issue(ci + 2, (ci + 2) % NSTAGE); CP_COMMIT(); }
        __syncthreads();
    }

    const int er = lane >> 2, ec = (lane & 3) * 2;
    float bv[8][2];
#pragma unroll
    for (int nt = 0; nt < 8; nt++) {
        bv[nt][0] = __ldg(bias + n0 + wn0 + nt * 8 + ec);
        bv[nt][1] = __ldg(bias + n0 + wn0 + nt * 8 + ec + 1);
    }
#pragma unroll
    for (int mi = 0; mi < 2; mi++) {
        int r0 = m0 + wm0 + mi * 16 + er;
        if (r0 < N_NODES) {
            float* h0 = H + (size_t)r0 * D + n0 + wn0 + ec;
#pragma unroll
            for (int nt = 0; nt < 8; nt++) {
                float2 o = make_float2(acc[mi][nt][0] + bv[nt][0],
                                       acc[mi][nt][1] + bv[nt][1]);
                *(float2*)(h0 + nt * 8) = o;
            }
        }
        int r1 = r0 + 8;
        if (r1 < N_NODES) {
            float* h1 = H + (size_t)r1 * D + n0 + wn0 + ec;
#pragma unroll
            for (int nt = 0; nt < 8; nt++) {
                float2 o = make_float2(acc[mi][nt][2] + bv[nt][0],
                                       acc[mi][nt][3] + bv[nt][1]);
                *(float2*)(h1 + nt * 8) = o;
            }
        }
    }
}

// ---------------- LayerNorm + ReLU + residual (+ fp16 out, row offset) ------
__global__ void __launch_bounds__(128) ln_kernel(
    const float* __restrict__ H, const float* __restrict__ Xin,
    const float* __restrict__ gg, const float* __restrict__ bb,
    float* __restrict__ Xout, __half* __restrict__ hi, int row0)
{
    int row = row0 + blockIdx.x;
    int t = threadIdx.x;
    int lane = t & 31, wid = t >> 5;

    float4 v = ((const float4*)(H + (size_t)row * D))[t];
    float s  = v.x + v.y + v.z + v.w;
    float sq = v.x * v.x + v.y * v.y + v.z * v.z + v.w * v.w;

#pragma unroll
    for (int off = 16; off > 0; off >>= 1) {
        s  += __shfl_xor_sync(0xFFFFFFFFu, s,  off);
        sq += __shfl_xor_sync(0xFFFFFFFFu, sq, off);
    }
    __shared__ float ss[4], sqs[4];
    if (lane == 0) { ss[wid] = s; sqs[wid] = sq; }
    __syncthreads();
    s  = ss[0]  + ss[1]  + ss[2]  + ss[3];
    sq = sqs[0] + sqs[1] + sqs[2] + sqs[3];

    float mean = s * (1.0f / D);
    float var  = sq * (1.0f / D) - mean * mean;
    float rr   = rsqrtf(var + LN_EPS);

    float4 g4 = ((const float4*)gg)[t];
    float4 b4 = ((const float4*)bb)[t];
    float4 xi = ((const float4*)(Xin + (size_t)row * D))[t];

    float4 o;
    o.x = fmaxf((v.x - mean) * rr * g4.x + b4.x, 0.f) + xi.x;
    o.y = fmaxf((v.y - mean) * rr * g4.y + b4.y, 0.f) + xi.y;
    o.z = fmaxf((v.z - mean) * rr * g4.z + b4.z, 0.f) + xi.z;
    o.w = fmaxf((v.w - mean) * rr * g4.w + b4.w, 0.f) + xi.w;
    ((float4*)(Xout + (size_t)row * D))[t] = o;

    __half2 p0 = __floats2half2_rn(o.x, o.y);
    __half2 p1 = __floats2half2_rn(o.z, o.w);
    ((uint2*)(hi + (size_t)row * D))[t] = make_uint2(h2u(p0), h2u(p1));
}

// ---------------- launch ----------------------------------------------------
extern "C" void kernel_launch(void* const* d_in, const int* in_sizes, int n_in,
                              void* d_out, int out_size)
{
    const float* x   = (const float*)d_in[0];
    const int*   ei  = (const int*)  d_in[1];
    const float* Wl  = (const float*)d_in[2];
    const float* Wr  = (const float*)d_in[3];
    const float* b   = (const float*)d_in[4];
    const float* lng = (const float*)d_in[5];
    const float* lnb = (const float*)d_in[6];
    float* out = (float*)d_out;

    float *h, *x0, *x1, *inv;
    int *deg, *rp, *cur, *bsum, *adj;
    __half *aH, *xH, *wl, *wr;
    cudaGetSymbolAddress((void**)&h,    g_h);
    cudaGetSymbolAddress((void**)&x0,   g_x0);
    cudaGetSymbolAddress((void**)&x1,   g_x1);
    cudaGetSymbolAddress((void**)&inv,  g_inv);
    cudaGetSymbolAddress((void**)&deg,  g_deg);
    cudaGetSymbolAddress((void**)&rp,   g_rp);
    cudaGetSymbolAddress((void**)&cur,  g_cur);
    cudaGetSymbolAddress((void**)&bsum, g_bsum);
    cudaGetSymbolAddress((void**)&adj,  g_adj);
    cudaGetSymbolAddress((void**)&aH,   g_aH);
    cudaGetSymbolAddress((void**)&xH,   g_xH);
    cudaGetSymbolAddress((void**)&wl,   g_wl);
    cudaGetSymbolAddress((void**)&wr,   g_wr);

    cudaFuncSetAttribute(gemm_tc_kernel,
                         cudaFuncAttributeMaxDynamicSharedMemorySize, GEMM_SMEM);

    cudaStream_t s2;
    cudaStreamCreateWithFlags(&s2, cudaStreamNonBlocking);
    cudaEvent_t evA[L_LAYERS][N_MCHUNK], evG[L_LAYERS][N_MCHUNK];
    for (int l = 0; l < L_LAYERS; l++)
        for (int c = 0; c < N_MCHUNK; c++) {
            cudaEventCreateWithFlags(&evA[l][c], cudaEventDisableTiming);
            cudaEventCreateWithFlags(&evG[l][c], cudaEventDisableTiming);
        }

    // ---- CSR build + fp16 conversions (serial on stream 0) ----
    zero_deg_kernel<<<(N_NODES + 255) / 256, 256>>>(deg);
    count_kernel<<<(N_EDGES + 255) / 256, 256>>>(ei, deg);
    scan1_kernel<<<SCAN_NBLK, SCAN_BS>>>(deg, rp, bsum);
    scan2_kernel<<<1, 256>>>(bsum);
    scan3_kernel<<<(N_NODES + 255) / 256, 256>>>(deg, rp, cur, inv, bsum);
    fill_kernel<<<(N_EDGES + 255) / 256, 256>>>(ei, cur, adj);

    tohalf_kernel<<<N_NODES, 128>>>(x, xH);
    tohalf_kernel<<<L_LAYERS * D, 128>>>(Wl, wl);
    tohalf_kernel<<<L_LAYERS * D, 128>>>(Wr, wr);

    const float* xin = x;
    float* outs[L_LAYERS] = { x0, x1, out };

    for (int l = 0; l < L_LAYERS; l++) {
        int mblk0[N_MCHUNK], nmblk[N_MCHUNK], nd0[N_MCHUNK], nd1[N_MCHUNK];
        for (int c = 0; c < N_MCHUNK; c++) {
            mblk0[c] = c * MBLK_PER_CHUNK;
            int e = mblk0[c] + MBLK_PER_CHUNK;
            if (e > MBLK_TOTAL) e = MBLK_TOTAL;
            nmblk[c] = e - mblk0[c];
            nd0[c] = mblk0[c] * 128;
            nd1[c] = e * 128; if (nd1[c] > N_NODES) nd1[c] = N_NODES;
        }

        for (int c = 0; c < N_MCHUNK; c++) {
            int nnodes = nd1[c] - nd0[c];
            agg_kernel<<<(nnodes + 7) / 8, 256>>>(xH, rp, deg, inv, adj,
                                                  aH, nd0[c], nd1[c]);
            cudaEventRecord(evA[l][c], 0);
        }
        for (int c = 0; c < N_MCHUNK; c++) {
            cudaStreamWaitEvent(s2, evA[l][c], 0);
            dim3 g(D / 128, nmblk[c]);
            gemm_tc_kernel<<<g, 256, GEMM_SMEM, s2>>>(
                aH, xH, wl + (size_t)l * D * D, wr + (size_t)l * D * D,
                b + (size_t)l * D, h, mblk0[c]);
            cudaEventRecord(evG[l][c], s2);
        }
        for (int c = 0; c < N_MCHUNK; c++) {
            cudaStreamWaitEvent(0, evG[l][c], 0);
            int nnodes = nd1[c] - nd0[c];
            ln_kernel<<<nnodes, 128>>>(h, xin, lng + (size_t)l * D,
                                       lnb + (size_t)l * D, outs[l],
                                       xH, nd0[c]);
        }
        xin = outs[l];
    }

    for (int l = 0; l < L_LAYERS; l++)
        for (int c = 0; c < N_MCHUNK; c++) {
            cudaEventDestroy(evA[l][c]);
            cudaEventDestroy(evG[l][c]);
        }
    cudaStreamDestroy(s2);
}